// round 12
// baseline (speedup 1.0000x reference)
#include <cuda_runtime.h>
#include <math.h>

// Capacity bounds (variants supported up to these; total scratch ~96 MB)
constexpr int  MAXH = 512;
constexpr int  MAXE = 8192;
constexpr long MAXN = 32768;

__device__ __align__(16) float g_K[(long)MAXH * MAXE];         // 16 MB
__device__ __align__(16) float g_M[(long)MAXH * MAXE];         // 16 MB
__device__ __align__(16) float g_c[MAXH];
__device__ __align__(16) float g_scores[MAXN * (long)MAXH];    // 64 MB (also K-split partial scratch)
__device__ int       g_is64;
__device__ int       g_H;
__device__ int       g_hub32[MAXH];
__device__ long long g_hub64[MAXH];

// ---------------------------------------------------------------------------
// Probe hub width by content and resolve H (unchanged — validated R10/R11).
// ---------------------------------------------------------------------------
__global__ void probe_normalize_kernel(const void* __restrict__ hub_raw,
                                       int c32, int c64, int verdict_n, long NN)
{
    __shared__ int s_is64, s_H;
    if (threadIdx.x == 0) {
        const long long* p64 = (const long long*)hub_raw;
        bool ok = true, nz = false;
        long long prev = -1;
        for (int i = 0; i < verdict_n; i++) {
            long long v = p64[i];
            if (v != 0) nz = true;
            if (v < 0 || v >= NN || v < prev) { ok = false; break; }
            prev = v;
        }
        s_is64 = (ok && nz) ? 1 : 0;
        s_H    = s_is64 ? c64 : c32;
        if (s_H > MAXH) s_H = MAXH;
        g_is64 = s_is64;
        g_H    = s_H;
    }
    __syncthreads();
    for (int i = threadIdx.x; i < s_H; i += blockDim.x) {
        long long v = s_is64 ? ((const long long*)hub_raw)[i]
                             : (long long)((const int*)hub_raw)[i];
        g_hub32[i] = (int)v;
        g_hub64[i] = v;
    }
}

// ---------------------------------------------------------------------------
// Double-buffered, bounds-guarded fp32 SGEMM with optional K-split (grid.z).
//   Czp[Mt,Nt] (row stride Cs) = A[Mt, k_off:k_off+Klen] * op(B) (+bias @z=0)
//   Czp = C + blockIdx.z * zStride;  k_off = blockIdx.z * Klen
//   TRANSB: B [Nt, ldb];  !TRANSB: B [K, ldb] row-major
//   GATHER: A row m = A[g_hub32[m], :]
//   Mt/Nt/Cs == -1 -> read g_H at runtime.
// One __syncthreads per K-tile; next tile's global loads issued pre-compute.
// ---------------------------------------------------------------------------
template<int BM, int BN, int BK, int TM, int TN, bool TRANSB, bool GATHER, bool BIAS>
__launch_bounds__((BM / TM) * (BN / TN))
__global__ void sgemm_db(const float* __restrict__ A,
                         const float* __restrict__ B,
                         const float* __restrict__ bias,
                         float*       __restrict__ C,
                         int Klen, int lda, int ldb,
                         int Mt_p, int Nt_p, int Cs_p, long zStride)
{
    constexpr int RT = BN / TN;
    constexpr int CT = BM / TM;
    constexpr int THREADS = RT * CT;
    constexpr int A_LD = (BM * BK) / (THREADS * 4);
    constexpr int B_LD = (BN * BK) / (THREADS * 4);
    static_assert(A_LD >= 1 && B_LD >= 1, "tile too small");
    static_assert((TM % 4) == 0 && (TN % 4) == 0, "vector ownership");

    const int Hdev = g_H;
    const int Mt = (Mt_p < 0) ? Hdev : Mt_p;
    const int Nt = (Nt_p < 0) ? Hdev : Nt_p;
    const int Cs = (Cs_p < 0) ? Hdev : Cs_p;
    const int k_off = blockIdx.z * Klen;
    float* Cz = C + (long)blockIdx.z * zStride;
    const bool doBias = BIAS && (blockIdx.z == 0);

    __shared__ __align__(16) float As[2][BK][BM];
    __shared__ __align__(16) float Bs[2][BK][BN];

    const int tx = threadIdx.x;
    const int tn = tx % RT;
    const int tm = tx / RT;
    const int m0 = blockIdx.y * BM;
    const int n0 = blockIdx.x * BN;

    float4 aR[A_LD], bR[B_LD];
    const int kTiles = Klen / BK;

    auto gld = [&](int k0) {
#pragma unroll
        for (int l = 0; l < A_LD; l++) {
            int slot = tx + l * THREADS;
            int m  = slot / (BK / 4);
            int kq = slot % (BK / 4);
            int mi = m0 + m; if (mi > Mt - 1) mi = Mt - 1;
            long row = GATHER ? (long)g_hub32[mi] : (long)mi;
            aR[l] = *reinterpret_cast<const float4*>(
                &A[row * (long)lda + k_off + k0 + kq * 4]);
        }
        if constexpr (TRANSB) {
#pragma unroll
            for (int l = 0; l < B_LD; l++) {
                int slot = tx + l * THREADS;
                int nn = slot / (BK / 4);
                int kq = slot % (BK / 4);
                int ni = n0 + nn; if (ni > Nt - 1) ni = Nt - 1;
                bR[l] = *reinterpret_cast<const float4*>(
                    &B[(long)ni * ldb + k_off + k0 + kq * 4]);
            }
        } else {
#pragma unroll
            for (int l = 0; l < B_LD; l++) {
                int slot = tx + l * THREADS;
                int k  = slot / (BN / 4);
                int nq = slot % (BN / 4);
                int nb = n0 + nq * 4;
                if (nb > Nt - 4) nb = (Nt >= 4) ? (Nt - 4) & ~3 : 0;
                bR[l] = *reinterpret_cast<const float4*>(
                    &B[(long)(k_off + k0 + k) * ldb + nb]);
            }
        }
    };
    auto sts = [&](int buf) {
#pragma unroll
        for (int l = 0; l < A_LD; l++) {
            int slot = tx + l * THREADS;
            int m  = slot / (BK / 4);
            int kq = slot % (BK / 4);
            As[buf][kq * 4 + 0][m] = aR[l].x;
            As[buf][kq * 4 + 1][m] = aR[l].y;
            As[buf][kq * 4 + 2][m] = aR[l].z;
            As[buf][kq * 4 + 3][m] = aR[l].w;
        }
        if constexpr (TRANSB) {
#pragma unroll
            for (int l = 0; l < B_LD; l++) {
                int slot = tx + l * THREADS;
                int nn = slot / (BK / 4);
                int kq = slot % (BK / 4);
                Bs[buf][kq * 4 + 0][nn] = bR[l].x;
                Bs[buf][kq * 4 + 1][nn] = bR[l].y;
                Bs[buf][kq * 4 + 2][nn] = bR[l].z;
                Bs[buf][kq * 4 + 3][nn] = bR[l].w;
            }
        } else {
#pragma unroll
            for (int l = 0; l < B_LD; l++) {
                int slot = tx + l * THREADS;
                int k  = slot / (BN / 4);
                int nq = slot % (BN / 4);
                *reinterpret_cast<float4*>(&Bs[buf][k][nq * 4]) = bR[l];
            }
        }
    };

    float acc[TM][TN];
#pragma unroll
    for (int j = 0; j < TM; j++)
#pragma unroll
        for (int i = 0; i < TN; i++) acc[j][i] = 0.f;

    gld(0);
    sts(0);
    __syncthreads();

    int cur = 0;
    for (int kt = 0; kt < kTiles; kt++) {
        if (kt + 1 < kTiles) gld((kt + 1) * BK);

#pragma unroll
        for (int kk = 0; kk < BK; kk++) {
            float ra[TM], rb[TN];
#pragma unroll
            for (int j = 0; j < TM; j += 4)
                *reinterpret_cast<float4*>(&ra[j]) =
                    *reinterpret_cast<const float4*>(&As[cur][kk][tm * TM + j]);
#pragma unroll
            for (int i = 0; i < TN; i += 4)
                *reinterpret_cast<float4*>(&rb[i]) =
                    *reinterpret_cast<const float4*>(&Bs[cur][kk][tn * TN + i]);
#pragma unroll
            for (int j = 0; j < TM; j++)
#pragma unroll
                for (int i = 0; i < TN; i++)
                    acc[j][i] = fmaf(ra[j], rb[i], acc[j][i]);
        }

        if (kt + 1 < kTiles) {
            sts(1 - cur);
            __syncthreads();
            cur ^= 1;
        }
    }

#pragma unroll
    for (int j = 0; j < TM; j++) {
        int m = m0 + tm * TM + j;
        if (m >= Mt) continue;
#pragma unroll
        for (int i = 0; i < TN; i++) {
            int n = n0 + tn * TN + i;
            if (n >= Nt) continue;
            float v = acc[j][i];
            if (doBias) v += bias[n];
            Cz[(long)m * Cs + n] = v;
        }
    }
}

// ---------------------------------------------------------------------------
// Deterministic K-split reduction: dst[i] = src[i] + src[zStride + i]
// ---------------------------------------------------------------------------
__global__ void reduce_add_kernel(float* __restrict__ dst,
                                  const float* __restrict__ src,
                                  long count, long zStride)
{
    long i = ((long)blockIdx.x * blockDim.x + threadIdx.x) * 4;
    if (i + 3 < count) {
        float4 a = *reinterpret_cast<const float4*>(&src[i]);
        float4 b = *reinterpret_cast<const float4*>(&src[zStride + i]);
        float4 r;
        r.x = a.x + b.x; r.y = a.y + b.y; r.z = a.z + b.z; r.w = a.w + b.w;
        *reinterpret_cast<float4*>(&dst[i]) = r;
    }
}

// ---------------------------------------------------------------------------
// c[h] = sum_e bq[e] * K[h,e]
// ---------------------------------------------------------------------------
__global__ void bias_c_kernel(const float* __restrict__ bq, int E)
{
    const int h = blockIdx.x;
    if (h >= g_H) return;
    __shared__ float red[256];
    float s = 0.f;
    for (int e = threadIdx.x; e < E; e += 256)
        s = fmaf(bq[e], g_K[(long)h * E + e], s);
    red[threadIdx.x] = s;
    __syncthreads();
    for (int off = 128; off > 0; off >>= 1) {
        if (threadIdx.x < off) red[threadIdx.x] += red[threadIdx.x + off];
        __syncthreads();
    }
    if (threadIdx.x == 0) g_c[h] = red[0];
}

// ---------------------------------------------------------------------------
// Per-row argmax (first index wins) + hub self-assignment -> f32 output.
// ---------------------------------------------------------------------------
__global__ void argmax_kernel(float* __restrict__ out, int N)
{
    const int gtid = blockIdx.x * blockDim.x + threadIdx.x;
    const int row  = gtid >> 5;
    const int lane = gtid & 31;
    if (row >= N) return;

    const int H = g_H;
    const float* s = g_scores + (long)row * H;
    float bv = -INFINITY;
    int   bi = 0;
    for (int h = lane; h < H; h += 32) {
        float v = s[h];
        if (v > bv) { bv = v; bi = h; }
    }
#pragma unroll
    for (int off = 16; off > 0; off >>= 1) {
        float ov = __shfl_down_sync(0xffffffffu, bv, off);
        int   oi = __shfl_down_sync(0xffffffffu, bi, off);
        if (ov > bv || (ov == bv && oi < bi)) { bv = ov; bi = oi; }
    }
    if (lane == 0) {
        int lo = 0, hi = H - 1;
        bool found = false;
        const long long rowv = (long long)row;
        while (lo <= hi) {
            int mid = (lo + hi) >> 1;
            long long v = g_hub64[mid];
            if (v == rowv) { found = true; break; }
            if (v < rowv) lo = mid + 1; else hi = mid - 1;
        }
        const long long val = found ? rowv : g_hub64[bi];
        out[row] = (float)val;
    }
}

static inline long isqrtl(long v) {
    long r = (long)(sqrt((double)v) + 0.5);
    while (r * r > v) r--;
    while ((r + 1) * (r + 1) <= v) r++;
    return r;
}

// ---------------------------------------------------------------------------
// Binding + dims derivation: byte-identical to R10/R11 (validated).
// ---------------------------------------------------------------------------
extern "C" void kernel_launch(void* const* d_in, const int* in_sizes, int n_in,
                              void* d_out, int out_size)
{
    long sz[16];
    int ord[16];
    int n = n_in > 16 ? 16 : n_in;
    for (int i = 0; i < n; i++) { sz[i] = (long)(unsigned)in_sizes[i]; ord[i] = i; }
    for (int a = 0; a < n; a++)
        for (int b = a + 1; b < n; b++)
            if (sz[ord[b]] > sz[ord[a]]) { int t = ord[a]; ord[a] = ord[b]; ord[b] = t; }

    const int sX = ord[0];
    const int wA = ord[1], wB = ord[2];
    const int sH = ord[n - 1];
    const int bA = (n >= 6) ? ord[3] : ord[1];
    const int bB = (n >= 6) ? ord[4] : ord[2];

    long E = 0, N = 0;
    int  c32 = 0, c64 = 0, verdict_n = 0;
    {
        long Ee = isqrtl(sz[wA]);
        bool okE = (Ee > 0) && (Ee * Ee == sz[wA]) && (sz[wA] == sz[wB]) &&
                   (sz[bA] == Ee) && (sz[bB] == Ee) &&
                   (sz[sX] % Ee == 0) && (Ee % 32 == 0);
        if (okE) {
            E = Ee; N = sz[sX] / Ee;
            c32 = (int)sz[sH]; c64 = (int)sz[sH];
            verdict_n = (int)(sz[sH] / 2);
        } else {
            long Eb = isqrtl(sz[wA] / 4);
            bool okB = (Eb > 0) && (Eb * Eb * 4 == sz[wA]) && (sz[wA] == sz[wB]) &&
                       (sz[bA] == Eb * 4) && (sz[bB] == Eb * 4) &&
                       (sz[sX] % (Eb * 4) == 0) && (Eb % 32 == 0);
            if (okB) {
                E = Eb; N = sz[sX] / 4 / Eb;
                c32 = (int)(sz[sH] / 4); c64 = (int)(sz[sH] / 8);
                verdict_n = c64;
            } else {
                E = 4096; N = 16384;
                c32 = 256; c64 = 256; verdict_n = 128;
            }
        }
    }
    if (E > MAXE) E = MAXE;
    if (N > MAXN) N = MAXN;
    if (N > (long)out_size) N = (long)out_size;
    int H_max = c32 > c64 ? c32 : c64;
    if (H_max > MAXH) H_max = MAXH;
    if (c32 > MAXH) c32 = MAXH;
    if (c64 > MAXH) c64 = MAXH;

    const int wlo = wA < wB ? wA : wB, whi = wA < wB ? wB : wA;
    const int blo = bA < bB ? bA : bB, bhi = bA < bB ? bB : bA;
    const bool x_first = (sX < wlo);
    const float* X   = (const float*)d_in[sX];
    const void*  hub = d_in[sH];
    const float* Wq  = (const float*)d_in[x_first ? wlo : whi];
    const float* Wk  = (const float*)d_in[x_first ? whi : wlo];
    const float* bq  = (const float*)d_in[x_first ? blo : bhi];
    const float* bk  = (const float*)d_in[x_first ? bhi : blo];

    float *pK, *pM, *pc, *pS;
    cudaGetSymbolAddress((void**)&pK, g_K);
    cudaGetSymbolAddress((void**)&pM, g_M);
    cudaGetSymbolAddress((void**)&pc, g_c);
    cudaGetSymbolAddress((void**)&pS, g_scores);

    const int iE = (int)E, iN = (int)N;
    auto cdiv = [](int a, int b) { return (a + b - 1) / b; };

    // K-split for stages 1/3 (deterministic: separate partials + fixed-order add)
    const int SPLIT = ((iE % 32) == 0) ? 2 : 1;       // Klen multiple of BK=16
    const int Klen  = iE / SPLIT;
    const long HE   = (long)H_max * iE;               // partial-buffer z-stride

    // 0) resolve hub width + H, normalize hub ids
    probe_normalize_kernel<<<1, 256>>>(hub, c32, c64, verdict_n, N);

    // 1) K = X[hub] @ Wk^T + bk  [H,E]  (K-split partials into g_scores)
    sgemm_db<64, 128, 16, 8, 8, true, true, true>
        <<<dim3(cdiv(iE, 128), cdiv(H_max, 64), SPLIT), 128>>>(
            X, Wk, bk, pS, Klen, iE, iE, -1, iE, iE, HE);
    if (SPLIT == 2)
        reduce_add_kernel<<<cdiv((int)(HE / 4), 256), 256>>>(pK, pS, HE, HE);
    else
        cudaMemcpyAsync(pK, pS, HE * sizeof(float), cudaMemcpyDeviceToDevice);

    // 2) c[h] = bq . K[h]
    bias_c_kernel<<<H_max, 256>>>(bq, iE);

    // 3) M = K @ Wq  [H,E]  (K-split partials into g_scores)
    sgemm_db<64, 128, 16, 8, 8, false, false, false>
        <<<dim3(cdiv(iE, 128), cdiv(H_max, 64), SPLIT), 128>>>(
            pK, Wq, nullptr, pS, Klen, iE, iE, -1, iE, iE, HE);
    if (SPLIT == 2)
        reduce_add_kernel<<<cdiv((int)(HE / 4), 256), 256>>>(pM, pS, HE, HE);
    else
        cudaMemcpyAsync(pM, pS, HE * sizeof(float), cudaMemcpyDeviceToDevice);

    // 4) scores = X @ M^T + c  [N,H]  (128x128, TM=8 TN=16 -> crossbar headroom)
    sgemm_db<128, 128, 16, 8, 16, true, false, true>
        <<<dim3(cdiv(H_max, 128), cdiv(iN, 128), 1), 128>>>(
            X, pM, pc, pS, iE, iE, iE, iN, -1, -1, 0);

    // 5) argmax + hub override -> f32 output
    argmax_kernel<<<cdiv(iN * 32, 256), 256>>>((float*)d_out, iN);
}

// round 14
// speedup vs baseline: 1.0644x; 1.0644x over previous
#include <cuda_runtime.h>
#include <math.h>

// Capacity bounds (variants supported up to these; total scratch ~96 MB)
constexpr int  MAXH = 512;
constexpr int  MAXE = 8192;
constexpr long MAXN = 32768;

__device__ __align__(16) float g_K[(long)MAXH * MAXE];         // 16 MB
__device__ __align__(16) float g_M[(long)MAXH * MAXE];         // 16 MB
__device__ __align__(16) float g_c[MAXH];
__device__ __align__(16) float g_scores[MAXN * (long)MAXH];    // 64 MB
__device__ int       g_is64;
__device__ int       g_H;
__device__ int       g_hub32[MAXH];
__device__ long long g_hub64[MAXH];

// ---- packed fp32x2 helpers (PTX f32x2 is a base sm_100-family feature) ----
__device__ __forceinline__ void fma2(unsigned long long& d,
                                     unsigned long long a,
                                     unsigned long long b)
{
    asm("fma.rn.f32x2 %0, %1, %2, %0;" : "+l"(d) : "l"(a), "l"(b));
}
__device__ __forceinline__ unsigned long long dup2(float x)
{
    unsigned long long r;
    asm("mov.b64 %0, {%1, %1};" : "=l"(r) : "f"(x));
    return r;
}
__device__ __forceinline__ void unpack2(unsigned long long v, float& lo, float& hi)
{
    asm("mov.b64 {%0, %1}, %2;" : "=f"(lo), "=f"(hi) : "l"(v));
}

// ---------------------------------------------------------------------------
// Probe hub width by content and resolve H (validated R10+).
// ---------------------------------------------------------------------------
__global__ void probe_normalize_kernel(const void* __restrict__ hub_raw,
                                       int c32, int c64, int verdict_n, long NN)
{
    __shared__ int s_is64, s_H;
    if (threadIdx.x == 0) {
        const long long* p64 = (const long long*)hub_raw;
        bool ok = true, nz = false;
        long long prev = -1;
        for (int i = 0; i < verdict_n; i++) {
            long long v = p64[i];
            if (v != 0) nz = true;
            if (v < 0 || v >= NN || v < prev) { ok = false; break; }
            prev = v;
        }
        s_is64 = (ok && nz) ? 1 : 0;
        s_H    = s_is64 ? c64 : c32;
        if (s_H > MAXH) s_H = MAXH;
        g_is64 = s_is64;
        g_H    = s_H;
    }
    __syncthreads();
    for (int i = threadIdx.x; i < s_H; i += blockDim.x) {
        long long v = s_is64 ? ((const long long*)hub_raw)[i]
                             : (long long)((const int*)hub_raw)[i];
        g_hub32[i] = (int)v;
        g_hub64[i] = v;
    }
}

// ---------------------------------------------------------------------------
// Double-buffered, bounds-guarded fp32 SGEMM — R11 structure with the inner
// product converted to packed FFMA2 (accumulator pairs along M; A pairs read
// directly from smem as 64-bit; B duplicated into both lanes).
// Per-lane IEEE fp32 FMA -> results bitwise identical to the scalar version.
// ---------------------------------------------------------------------------
template<int BM, int BN, int BK, int TM, int TN, bool TRANSB, bool GATHER, bool BIAS>
__launch_bounds__((BM / TM) * (BN / TN))
__global__ void sgemm_db(const float* __restrict__ A,
                         const float* __restrict__ B,
                         const float* __restrict__ bias,
                         float*       __restrict__ C,
                         int Kdim, int Mt_p, int Nt_p, int Cs_p)
{
    constexpr int RT = BN / TN;
    constexpr int CT = BM / TM;
    constexpr int THREADS = RT * CT;
    constexpr int A_LD = (BM * BK) / (THREADS * 4);
    constexpr int B_LD = (BN * BK) / (THREADS * 4);
    static_assert(A_LD >= 1 && B_LD >= 1, "tile too small");
    static_assert((TM % 2) == 0 && (TN % 4) == 0, "pairing/vector ownership");

    const int Hdev = g_H;
    const int Mt = (Mt_p < 0) ? Hdev : Mt_p;
    const int Nt = (Nt_p < 0) ? Hdev : Nt_p;
    const int Cs = (Cs_p < 0) ? Hdev : Cs_p;

    __shared__ __align__(16) float As[2][BK][BM];
    __shared__ __align__(16) float Bs[2][BK][BN];

    const int tx = threadIdx.x;
    const int tn = tx % RT;
    const int tm = tx / RT;
    const int m0 = blockIdx.y * BM;
    const int n0 = blockIdx.x * BN;

    float4 aR[A_LD], bR[B_LD];
    const int kTiles = Kdim / BK;

    auto gld = [&](int k0) {
#pragma unroll
        for (int l = 0; l < A_LD; l++) {
            int slot = tx + l * THREADS;
            int m  = slot / (BK / 4);
            int kq = slot % (BK / 4);
            int mi = m0 + m; if (mi > Mt - 1) mi = Mt - 1;
            long row = GATHER ? (long)g_hub32[mi] : (long)mi;
            aR[l] = *reinterpret_cast<const float4*>(&A[row * (long)Kdim + k0 + kq * 4]);
        }
        if constexpr (TRANSB) {
#pragma unroll
            for (int l = 0; l < B_LD; l++) {
                int slot = tx + l * THREADS;
                int nn = slot / (BK / 4);
                int kq = slot % (BK / 4);
                int ni = n0 + nn; if (ni > Nt - 1) ni = Nt - 1;
                bR[l] = *reinterpret_cast<const float4*>(&B[(long)ni * Kdim + k0 + kq * 4]);
            }
        } else {
#pragma unroll
            for (int l = 0; l < B_LD; l++) {
                int slot = tx + l * THREADS;
                int k  = slot / (BN / 4);
                int nq = slot % (BN / 4);
                int nb = n0 + nq * 4;
                if (nb > Nt - 4) nb = (Nt >= 4) ? (Nt - 4) & ~3 : 0;
                bR[l] = *reinterpret_cast<const float4*>(&B[(long)(k0 + k) * Cs + nb]);
            }
        }
    };
    auto sts = [&](int buf) {
#pragma unroll
        for (int l = 0; l < A_LD; l++) {
            int slot = tx + l * THREADS;
            int m  = slot / (BK / 4);
            int kq = slot % (BK / 4);
            As[buf][kq * 4 + 0][m] = aR[l].x;
            As[buf][kq * 4 + 1][m] = aR[l].y;
            As[buf][kq * 4 + 2][m] = aR[l].z;
            As[buf][kq * 4 + 3][m] = aR[l].w;
        }
        if constexpr (TRANSB) {
#pragma unroll
            for (int l = 0; l < B_LD; l++) {
                int slot = tx + l * THREADS;
                int nn = slot / (BK / 4);
                int kq = slot % (BK / 4);
                Bs[buf][kq * 4 + 0][nn] = bR[l].x;
                Bs[buf][kq * 4 + 1][nn] = bR[l].y;
                Bs[buf][kq * 4 + 2][nn] = bR[l].z;
                Bs[buf][kq * 4 + 3][nn] = bR[l].w;
            }
        } else {
#pragma unroll
            for (int l = 0; l < B_LD; l++) {
                int slot = tx + l * THREADS;
                int k  = slot / (BN / 4);
                int nq = slot % (BN / 4);
                *reinterpret_cast<float4*>(&Bs[buf][k][nq * 4]) = bR[l];
            }
        }
    };

    // packed accumulators: lane pair = M-rows (2p, 2p+1) at column i
    unsigned long long acc2[TM / 2][TN];
#pragma unroll
    for (int p = 0; p < TM / 2; p++)
#pragma unroll
        for (int i = 0; i < TN; i++) acc2[p][i] = 0ULL;

    gld(0); sts(0); __syncthreads();
    int cur = 0;
    for (int kt = 0; kt < kTiles; kt++) {
        if (kt + 1 < kTiles) gld((kt + 1) * BK);
#pragma unroll
        for (int kk = 0; kk < BK; kk++) {
            // A pairs straight from smem (rows adjacent in As layout)
            unsigned long long rap[TM / 2];
            const unsigned long long* ap =
                reinterpret_cast<const unsigned long long*>(&As[cur][kk][tm * TM]);
#pragma unroll
            for (int p = 0; p < TM / 2; p++) rap[p] = ap[p];
            // B fragment + duplicate into both lanes
            float rb[TN];
#pragma unroll
            for (int i = 0; i < TN; i += 4)
                *reinterpret_cast<float4*>(&rb[i]) =
                    *reinterpret_cast<const float4*>(&Bs[cur][kk][tn * TN + i]);
            unsigned long long rbp[TN];
#pragma unroll
            for (int i = 0; i < TN; i++) rbp[i] = dup2(rb[i]);
#pragma unroll
            for (int p = 0; p < TM / 2; p++)
#pragma unroll
                for (int i = 0; i < TN; i++)
                    fma2(acc2[p][i], rap[p], rbp[i]);
        }
        if (kt + 1 < kTiles) { sts(1 - cur); __syncthreads(); cur ^= 1; }
    }

    // ---- epilogue: unpack pairs, bias, guarded stores
#pragma unroll
    for (int p = 0; p < TM / 2; p++) {
        const int m_lo = m0 + tm * TM + 2 * p;
        const int m_hi = m_lo + 1;
#pragma unroll
        for (int i = 0; i < TN; i++) {
            int nn = n0 + tn * TN + i;
            if (nn >= Nt) continue;
            float lo, hi;
            unpack2(acc2[p][i], lo, hi);
            float bv = 0.f;
            if constexpr (BIAS) bv = bias[nn];
            if (m_lo < Mt) C[(long)m_lo * Cs + nn] = lo + bv;
            if (m_hi < Mt) C[(long)m_hi * Cs + nn] = hi + bv;
        }
    }
}

// ---------------------------------------------------------------------------
__global__ void bias_c_kernel(const float* __restrict__ bq, int E)
{
    const int h = blockIdx.x;
    if (h >= g_H) return;
    __shared__ float red[256];
    float s = 0.f;
    for (int e = threadIdx.x; e < E; e += 256)
        s = fmaf(bq[e], g_K[(long)h * E + e], s);
    red[threadIdx.x] = s;
    __syncthreads();
    for (int off = 128; off > 0; off >>= 1) {
        if (threadIdx.x < off) red[threadIdx.x] += red[threadIdx.x + off];
        __syncthreads();
    }
    if (threadIdx.x == 0) g_c[h] = red[0];
}

// ---------------------------------------------------------------------------
// Per-row argmax (first index wins) + hub self-assignment -> f32 output.
// ---------------------------------------------------------------------------
__global__ void argmax_kernel(float* __restrict__ out, int N)
{
    const int gtid = blockIdx.x * blockDim.x + threadIdx.x;
    const int row  = gtid >> 5;
    const int lane = gtid & 31;
    if (row >= N) return;
    const int H = g_H;
    const float* s = g_scores + (long)row * H;
    float bv = -INFINITY;
    int   bi = 0;
    for (int h = lane; h < H; h += 32) {
        float v = s[h];
        if (v > bv) { bv = v; bi = h; }
    }
#pragma unroll
    for (int off = 16; off > 0; off >>= 1) {
        float ov = __shfl_down_sync(0xffffffffu, bv, off);
        int   oi = __shfl_down_sync(0xffffffffu, bi, off);
        if (ov > bv || (ov == bv && oi < bi)) { bv = ov; bi = oi; }
    }
    if (lane == 0) {
        int lo = 0, hi = H - 1;
        bool found = false;
        const long long rowv = (long long)row;
        while (lo <= hi) {
            int mid = (lo + hi) >> 1;
            long long v = g_hub64[mid];
            if (v == rowv) { found = true; break; }
            if (v < rowv) lo = mid + 1; else hi = mid - 1;
        }
        out[row] = found ? (float)rowv : (float)g_hub64[bi];
    }
}

static inline long isqrtl(long v) {
    long r = (long)(sqrt((double)v) + 0.5);
    while (r * r > v) r--;
    while ((r + 1) * (r + 1) <= v) r++;
    return r;
}

// ---------------------------------------------------------------------------
// Binding + dims derivation: byte-identical to R10/R11 (validated).
// ---------------------------------------------------------------------------
extern "C" void kernel_launch(void* const* d_in, const int* in_sizes, int n_in,
                              void* d_out, int out_size)
{
    long sz[16];
    int ord[16];
    int n = n_in > 16 ? 16 : n_in;
    for (int i = 0; i < n; i++) { sz[i] = (long)(unsigned)in_sizes[i]; ord[i] = i; }
    for (int a = 0; a < n; a++)
        for (int b = a + 1; b < n; b++)
            if (sz[ord[b]] > sz[ord[a]]) { int t = ord[a]; ord[a] = ord[b]; ord[b] = t; }

    const int sX = ord[0];
    const int wA = ord[1], wB = ord[2];
    const int sH = ord[n - 1];
    const int bA = (n >= 6) ? ord[3] : ord[1];
    const int bB = (n >= 6) ? ord[4] : ord[2];

    long E = 0, N = 0;
    int  c32 = 0, c64 = 0, verdict_n = 0;
    {
        long Ee = isqrtl(sz[wA]);
        bool okE = (Ee > 0) && (Ee * Ee == sz[wA]) && (sz[wA] == sz[wB]) &&
                   (sz[bA] == Ee) && (sz[bB] == Ee) &&
                   (sz[sX] % Ee == 0) && (Ee % 32 == 0);
        if (okE) {
            E = Ee; N = sz[sX] / Ee;
            c32 = (int)sz[sH]; c64 = (int)sz[sH];
            verdict_n = (int)(sz[sH] / 2);
        } else {
            long Eb = isqrtl(sz[wA] / 4);
            bool okB = (Eb > 0) && (Eb * Eb * 4 == sz[wA]) && (sz[wA] == sz[wB]) &&
                       (sz[bA] == Eb * 4) && (sz[bB] == Eb * 4) &&
                       (sz[sX] % (Eb * 4) == 0) && (Eb % 32 == 0);
            if (okB) {
                E = Eb; N = sz[sX] / 4 / Eb;
                c32 = (int)(sz[sH] / 4); c64 = (int)(sz[sH] / 8);
                verdict_n = c64;
            } else {
                E = 4096; N = 16384;
                c32 = 256; c64 = 256; verdict_n = 128;
            }
        }
    }
    if (E > MAXE) E = MAXE;
    if (N > MAXN) N = MAXN;
    if (N > (long)out_size) N = (long)out_size;
    int H_max = c32 > c64 ? c32 : c64;
    if (H_max > MAXH) H_max = MAXH;
    if (c32 > MAXH) c32 = MAXH;
    if (c64 > MAXH) c64 = MAXH;

    const int wlo = wA < wB ? wA : wB, whi = wA < wB ? wB : wA;
    const int blo = bA < bB ? bA : bB, bhi = bA < bB ? bB : bA;
    const bool x_first = (sX < wlo);
    const float* X   = (const float*)d_in[sX];
    const void*  hub = d_in[sH];
    const float* Wq  = (const float*)d_in[x_first ? wlo : whi];
    const float* Wk  = (const float*)d_in[x_first ? whi : wlo];
    const float* bq  = (const float*)d_in[x_first ? blo : bhi];
    const float* bk  = (const float*)d_in[x_first ? bhi : blo];

    float *pK, *pM, *pc, *pS;
    cudaGetSymbolAddress((void**)&pK, g_K);
    cudaGetSymbolAddress((void**)&pM, g_M);
    cudaGetSymbolAddress((void**)&pc, g_c);
    cudaGetSymbolAddress((void**)&pS, g_scores);

    const int iE = (int)E, iN = (int)N;
    auto cdiv = [](int a, int b) { return (a + b - 1) / b; };

    // 0) resolve hub width + H, normalize hub ids
    probe_normalize_kernel<<<1, 256>>>(hub, c32, c64, verdict_n, N);

    // 1) K = X[hub] @ Wk^T + bk        [H, E]   (R11 config, FFMA2 core)
    sgemm_db<64, 64, 32, 4, 4, true, true, true>
        <<<dim3(cdiv(iE, 64), cdiv(H_max, 64)), 256>>>(X, Wk, bk, pK, iE, -1, iE, iE);

    // 2) c[h] = bq . K[h]
    bias_c_kernel<<<H_max, 256>>>(bq, iE);

    // 3) M = K @ Wq                    [H, E]   (R11 config, FFMA2 core)
    sgemm_db<64, 64, 32, 4, 4, false, false, false>
        <<<dim3(cdiv(iE, 64), cdiv(H_max, 64)), 256>>>(pK, Wq, nullptr, pM, iE, -1, iE, iE);

    // 4) scores = X @ M^T + c          [N, H]   (R11 config, FFMA2 core)
    sgemm_db<128, 128, 16, 8, 8, true, false, true>
        <<<dim3(cdiv(H_max, 128), cdiv(iN, 128)), 256>>>(X, pM, pc, pS, iE, iN, -1, -1);

    // 5) argmax + hub override -> f32 output
    argmax_kernel<<<cdiv(iN * 32, 256), 256>>>((float*)d_out, iN);
}

// round 15
// speedup vs baseline: 1.1499x; 1.0804x over previous
#include <cuda_runtime.h>
#include <cuda_bf16.h>
#include <math.h>
#include <stdint.h>

// Capacity bounds (total static scratch ~104 MB)
constexpr int  MAXH = 512;
constexpr int  MAXE = 8192;
constexpr long MAXN = 32768;

__device__ __align__(16) float g_K[(long)MAXH * MAXE];         // 16 MB
__device__ __align__(16) float g_M[(long)MAXH * MAXE];         // 16 MB
__device__ __align__(16) float g_c[MAXH];
__device__ __align__(16) float g_scores[MAXN * (long)MAXH];    // 64 MB
__device__ __align__(16) __nv_bfloat16 g_Mh[(long)MAXH * MAXE];// 8 MB
__device__ int       g_is64;
__device__ int       g_H;
__device__ int       g_hub32[MAXH];
__device__ long long g_hub64[MAXH];

__device__ __forceinline__ __nv_bfloat162 u2b(uint32_t u) {
    return *reinterpret_cast<__nv_bfloat162*>(&u);
}
__device__ __forceinline__ uint32_t b2u(__nv_bfloat162 b) {
    return *reinterpret_cast<uint32_t*>(&b);
}

// ---------------------------------------------------------------------------
// Probe hub width by content and resolve H (validated R10+).
// ---------------------------------------------------------------------------
__global__ void probe_normalize_kernel(const void* __restrict__ hub_raw,
                                       int c32, int c64, int verdict_n, long NN)
{
    __shared__ int s_is64, s_H;
    if (threadIdx.x == 0) {
        const long long* p64 = (const long long*)hub_raw;
        bool ok = true, nz = false;
        long long prev = -1;
        for (int i = 0; i < verdict_n; i++) {
            long long v = p64[i];
            if (v != 0) nz = true;
            if (v < 0 || v >= NN || v < prev) { ok = false; break; }
            prev = v;
        }
        s_is64 = (ok && nz) ? 1 : 0;
        s_H    = s_is64 ? c64 : c32;
        if (s_H > MAXH) s_H = MAXH;
        g_is64 = s_is64;
        g_H    = s_H;
    }
    __syncthreads();
    for (int i = threadIdx.x; i < s_H; i += blockDim.x) {
        long long v = s_is64 ? ((const long long*)hub_raw)[i]
                             : (long long)((const int*)hub_raw)[i];
        g_hub32[i] = (int)v;
        g_hub64[i] = v;
    }
}

// ---------------------------------------------------------------------------
// fp32 SGEMM (validated R11/R14 structure, scalar core) — stages 1/3 + fallback.
// ---------------------------------------------------------------------------
template<int BM, int BN, int BK, int TM, int TN, bool TRANSB, bool GATHER, bool BIAS>
__launch_bounds__((BM / TM) * (BN / TN))
__global__ void sgemm_db(const float* __restrict__ A,
                         const float* __restrict__ B,
                         const float* __restrict__ bias,
                         float*       __restrict__ C,
                         int Kdim, int Mt_p, int Nt_p, int Cs_p)
{
    constexpr int RT = BN / TN;
    constexpr int CT = BM / TM;
    constexpr int THREADS = RT * CT;
    constexpr int A_LD = (BM * BK) / (THREADS * 4);
    constexpr int B_LD = (BN * BK) / (THREADS * 4);
    static_assert(A_LD >= 1 && B_LD >= 1, "tile too small");

    const int Hdev = g_H;
    const int Mt = (Mt_p < 0) ? Hdev : Mt_p;
    const int Nt = (Nt_p < 0) ? Hdev : Nt_p;
    const int Cs = (Cs_p < 0) ? Hdev : Cs_p;

    __shared__ __align__(16) float As[2][BK][BM];
    __shared__ __align__(16) float Bs[2][BK][BN];

    const int tx = threadIdx.x;
    const int tn = tx % RT;
    const int tm = tx / RT;
    const int m0 = blockIdx.y * BM;
    const int n0 = blockIdx.x * BN;

    float4 aR[A_LD], bR[B_LD];
    const int kTiles = Kdim / BK;

    auto gld = [&](int k0) {
#pragma unroll
        for (int l = 0; l < A_LD; l++) {
            int slot = tx + l * THREADS;
            int m  = slot / (BK / 4);
            int kq = slot % (BK / 4);
            int mi = m0 + m; if (mi > Mt - 1) mi = Mt - 1;
            long row = GATHER ? (long)g_hub32[mi] : (long)mi;
            aR[l] = *reinterpret_cast<const float4*>(&A[row * (long)Kdim + k0 + kq * 4]);
        }
        if constexpr (TRANSB) {
#pragma unroll
            for (int l = 0; l < B_LD; l++) {
                int slot = tx + l * THREADS;
                int nn = slot / (BK / 4);
                int kq = slot % (BK / 4);
                int ni = n0 + nn; if (ni > Nt - 1) ni = Nt - 1;
                bR[l] = *reinterpret_cast<const float4*>(&B[(long)ni * Kdim + k0 + kq * 4]);
            }
        } else {
#pragma unroll
            for (int l = 0; l < B_LD; l++) {
                int slot = tx + l * THREADS;
                int k  = slot / (BN / 4);
                int nq = slot % (BN / 4);
                int nb = n0 + nq * 4;
                if (nb > Nt - 4) nb = (Nt >= 4) ? (Nt - 4) & ~3 : 0;
                bR[l] = *reinterpret_cast<const float4*>(&B[(long)(k0 + k) * Cs + nb]);
            }
        }
    };
    auto sts = [&](int buf) {
#pragma unroll
        for (int l = 0; l < A_LD; l++) {
            int slot = tx + l * THREADS;
            int m  = slot / (BK / 4);
            int kq = slot % (BK / 4);
            As[buf][kq * 4 + 0][m] = aR[l].x;
            As[buf][kq * 4 + 1][m] = aR[l].y;
            As[buf][kq * 4 + 2][m] = aR[l].z;
            As[buf][kq * 4 + 3][m] = aR[l].w;
        }
        if constexpr (TRANSB) {
#pragma unroll
            for (int l = 0; l < B_LD; l++) {
                int slot = tx + l * THREADS;
                int nn = slot / (BK / 4);
                int kq = slot % (BK / 4);
                Bs[buf][kq * 4 + 0][nn] = bR[l].x;
                Bs[buf][kq * 4 + 1][nn] = bR[l].y;
                Bs[buf][kq * 4 + 2][nn] = bR[l].z;
                Bs[buf][kq * 4 + 3][nn] = bR[l].w;
            }
        } else {
#pragma unroll
            for (int l = 0; l < B_LD; l++) {
                int slot = tx + l * THREADS;
                int k  = slot / (BN / 4);
                int nq = slot % (BN / 4);
                *reinterpret_cast<float4*>(&Bs[buf][k][nq * 4]) = bR[l];
            }
        }
    };

    float acc[TM][TN];
#pragma unroll
    for (int j = 0; j < TM; j++)
#pragma unroll
        for (int i = 0; i < TN; i++) acc[j][i] = 0.f;

    gld(0); sts(0); __syncthreads();
    int cur = 0;
    for (int kt = 0; kt < kTiles; kt++) {
        if (kt + 1 < kTiles) gld((kt + 1) * BK);
#pragma unroll
        for (int kk = 0; kk < BK; kk++) {
            float ra[TM], rb[TN];
#pragma unroll
            for (int j = 0; j < TM; j += 4)
                *reinterpret_cast<float4*>(&ra[j]) =
                    *reinterpret_cast<const float4*>(&As[cur][kk][tm * TM + j]);
#pragma unroll
            for (int i = 0; i < TN; i += 4)
                *reinterpret_cast<float4*>(&rb[i]) =
                    *reinterpret_cast<const float4*>(&Bs[cur][kk][tn * TN + i]);
#pragma unroll
            for (int j = 0; j < TM; j++)
#pragma unroll
                for (int i = 0; i < TN; i++)
                    acc[j][i] = fmaf(ra[j], rb[i], acc[j][i]);
        }
        if (kt + 1 < kTiles) { sts(1 - cur); __syncthreads(); cur ^= 1; }
    }
#pragma unroll
    for (int j = 0; j < TM; j++) {
        int m = m0 + tm * TM + j;
        if (m >= Mt) continue;
#pragma unroll
        for (int i = 0; i < TN; i++) {
            int n = n0 + tn * TN + i;
            if (n >= Nt) continue;
            float v = acc[j][i];
            if constexpr (BIAS) v += bias[n];
            C[(long)m * Cs + n] = v;
        }
    }
}

// ---------------------------------------------------------------------------
__global__ void bias_c_kernel(const float* __restrict__ bq, int E)
{
    const int h = blockIdx.x;
    if (h >= g_H) return;
    __shared__ float red[256];
    float s = 0.f;
    for (int e = threadIdx.x; e < E; e += 256)
        s = fmaf(bq[e], g_K[(long)h * E + e], s);
    red[threadIdx.x] = s;
    __syncthreads();
    for (int off = 128; off > 0; off >>= 1) {
        if (threadIdx.x < off) red[threadIdx.x] += red[threadIdx.x + off];
        __syncthreads();
    }
    if (threadIdx.x == 0) g_c[h] = red[0];
}

// M -> bf16 (single rounding)
__global__ void mh_convert_kernel(int H, int E)
{
    const long total = (long)H * E;
    for (long i = (long)blockIdx.x * blockDim.x + threadIdx.x;
         i < total; i += (long)gridDim.x * blockDim.x)
        g_Mh[i] = __float2bfloat16(g_M[i]);
}

// ===========================================================================
// Approximate scores via bf16 HFMA2 (2 MAC/instr): BM=128 rows x BN=64 hubs,
// 32 K per tile packed as 16 bf16x2 pairs. Chunk accumulators in bf16x2,
// flushed to fp32 per tile (32-K chunks keep partial-sum rounding tame).
// Writes s_approx + c into g_scores. Requires E%32==0, N%128==0, H%64==0.
// ===========================================================================
__global__ __launch_bounds__(256)
void score_bf16(const float* __restrict__ X, int E, int H)
{
    constexpr int BM = 128, BN = 64, BKP = 16;
    __shared__ __align__(16) uint32_t As[2][BKP][BM];
    __shared__ __align__(16) uint32_t Bs[2][BKP][BN];

    const int tx = threadIdx.x;
    const int tn = tx & 15;          // 16 groups -> TN=4
    const int tm = tx >> 4;          // 16 groups -> TM=8
    const int r0 = blockIdx.y * BM;
    const int n0 = blockIdx.x * BN;

    float4 aR[4];
    uint4  bRv;
    const int tiles = E / 32;

    auto gld = [&](int k0) {
#pragma unroll
        for (int l = 0; l < 4; l++) {
            int slot = tx + l * 256;
            int m = slot >> 3;
            int q = slot & 7;
            aR[l] = *reinterpret_cast<const float4*>(&X[(long)(r0 + m) * E + k0 + q * 4]);
        }
        {
            int h = tx >> 2;
            int q = tx & 3;
            bRv = *reinterpret_cast<const uint4*>(&g_Mh[(long)(n0 + h) * E + k0 + q * 8]);
        }
    };
    auto sts = [&](int buf) {
#pragma unroll
        for (int l = 0; l < 4; l++) {
            int slot = tx + l * 256;
            int m = slot >> 3;
            int q = slot & 7;
            As[buf][2 * q + 0][m] = b2u(__float22bfloat162_rn(make_float2(aR[l].x, aR[l].y)));
            As[buf][2 * q + 1][m] = b2u(__float22bfloat162_rn(make_float2(aR[l].z, aR[l].w)));
        }
        {
            int h = tx >> 2;
            int q = tx & 3;
            Bs[buf][4 * q + 0][h] = bRv.x;
            Bs[buf][4 * q + 1][h] = bRv.y;
            Bs[buf][4 * q + 2][h] = bRv.z;
            Bs[buf][4 * q + 3][h] = bRv.w;
        }
    };

    float accf[8][4];
#pragma unroll
    for (int j = 0; j < 8; j++)
#pragma unroll
        for (int i = 0; i < 4; i++) accf[j][i] = 0.f;

    gld(0); sts(0); __syncthreads();
    int cur = 0;
    const __nv_bfloat162 z2 = __float2bfloat162_rn(0.f);

    for (int t = 0; t < tiles; t++) {
        if (t + 1 < tiles) gld((t + 1) * 32);

        __nv_bfloat162 acc2[8][4];
#pragma unroll
        for (int j = 0; j < 8; j++)
#pragma unroll
            for (int i = 0; i < 4; i++) acc2[j][i] = z2;

#pragma unroll
        for (int kp = 0; kp < BKP; kp++) {
            uint32_t ra[8], rb[4];
            *reinterpret_cast<uint4*>(&ra[0]) =
                *reinterpret_cast<const uint4*>(&As[cur][kp][tm * 8]);
            *reinterpret_cast<uint4*>(&ra[4]) =
                *reinterpret_cast<const uint4*>(&As[cur][kp][tm * 8 + 4]);
            *reinterpret_cast<uint4*>(&rb[0]) =
                *reinterpret_cast<const uint4*>(&Bs[cur][kp][tn * 4]);
#pragma unroll
            for (int j = 0; j < 8; j++)
#pragma unroll
                for (int i = 0; i < 4; i++)
                    acc2[j][i] = __hfma2(u2b(ra[j]), u2b(rb[i]), acc2[j][i]);
        }
        // flush chunk to fp32
#pragma unroll
        for (int j = 0; j < 8; j++)
#pragma unroll
            for (int i = 0; i < 4; i++) {
                float2 f = __bfloat1622float2(acc2[j][i]);
                accf[j][i] += f.x + f.y;
            }

        if (t + 1 < tiles) { sts(1 - cur); __syncthreads(); cur ^= 1; }
    }

#pragma unroll
    for (int j = 0; j < 8; j++) {
        const int m = r0 + tm * 8 + j;
#pragma unroll
        for (int i = 0; i < 4; i++) {
            const int h = n0 + tn * 4 + i;
            g_scores[(long)m * H + h] = accf[j][i] + g_c[h];
        }
    }
}

// ===========================================================================
// Argmax with exact rescoring of near-ties. Warp per row:
//  - best/mean/var over approx scores; delta = 0.1 * row-sigma (~12 sigma_e)
//  - single candidate -> done; else exact fp32 dot for each candidate
//    (first-wins in h order), which dominates all non-candidates.
// ===========================================================================
__global__ void argmax_rescore(const float* __restrict__ X,
                               const float* __restrict__ Mx,
                               float* __restrict__ out, int E, int N)
{
    const int gtid = blockIdx.x * blockDim.x + threadIdx.x;
    const int row  = gtid >> 5;
    const int lane = gtid & 31;
    if (row >= N) return;

    const int H = g_H;
    const float* s = g_scores + (long)row * H;

    float bv = -INFINITY; int bi = 0;
    float sum = 0.f, sum2 = 0.f;
    for (int h = lane; h < H; h += 32) {
        float v = s[h];
        sum += v; sum2 += v * v;
        if (v > bv) { bv = v; bi = h; }
    }
#pragma unroll
    for (int off = 16; off > 0; off >>= 1) {
        float ov = __shfl_xor_sync(0xffffffffu, bv, off);
        int   oi = __shfl_xor_sync(0xffffffffu, bi, off);
        if (ov > bv || (ov == bv && oi < bi)) { bv = ov; bi = oi; }
        sum  += __shfl_xor_sync(0xffffffffu, sum,  off);
        sum2 += __shfl_xor_sync(0xffffffffu, sum2, off);
    }
    const float mean = sum / H;
    const float var  = fmaxf(sum2 / H - mean * mean, 0.f);
    const float delta = 0.10f * sqrtf(var) + 1e-20f;
    const float thr = bv - delta;

    // count candidates
    int cnt = 0;
    for (int h = lane; h < H; h += 32)
        if (s[h] >= thr) cnt++;
#pragma unroll
    for (int off = 16; off > 0; off >>= 1)
        cnt += __shfl_xor_sync(0xffffffffu, cnt, off);

    int pick = bi;
    if (cnt > 1) {
        float bestE = -INFINITY; int bestH = 0;
        for (int h = 0; h < H; h++) {
            if (s[h] < thr) continue;              // uniform across warp
            float part = 0.f;
            const float* xr = X  + (long)row * E;
            const float* mr = Mx + (long)h   * E;
            for (int e = lane * 4; e < E; e += 128) {
                float4 xv = *reinterpret_cast<const float4*>(&xr[e]);
                float4 mv = *reinterpret_cast<const float4*>(&mr[e]);
                part = fmaf(xv.x, mv.x, part);
                part = fmaf(xv.y, mv.y, part);
                part = fmaf(xv.z, mv.z, part);
                part = fmaf(xv.w, mv.w, part);
            }
#pragma unroll
            for (int off = 16; off > 0; off >>= 1)
                part += __shfl_xor_sync(0xffffffffu, part, off);
            float ex = part + g_c[h];
            if (ex > bestE) { bestE = ex; bestH = h; }   // first-wins in h
        }
        pick = bestH;
    }

    if (lane == 0) {
        int lo = 0, hi = H - 1;
        bool found = false;
        const long long rowv = (long long)row;
        while (lo <= hi) {
            int mid = (lo + hi) >> 1;
            long long v = g_hub64[mid];
            if (v == rowv) { found = true; break; }
            if (v < rowv) lo = mid + 1; else hi = mid - 1;
        }
        out[row] = found ? (float)rowv : (float)g_hub64[pick];
    }
}

// ---------------- fallback SIMT argmax (R14, validated) --------------------
__global__ void argmax_kernel(float* __restrict__ out, int N)
{
    const int gtid = blockIdx.x * blockDim.x + threadIdx.x;
    const int row  = gtid >> 5;
    const int lane = gtid & 31;
    if (row >= N) return;
    const int H = g_H;
    const float* s = g_scores + (long)row * H;
    float bv = -INFINITY;
    int   bi = 0;
    for (int h = lane; h < H; h += 32) {
        float v = s[h];
        if (v > bv) { bv = v; bi = h; }
    }
#pragma unroll
    for (int off = 16; off > 0; off >>= 1) {
        float ov = __shfl_down_sync(0xffffffffu, bv, off);
        int   oi = __shfl_down_sync(0xffffffffu, bi, off);
        if (ov > bv || (ov == bv && oi < bi)) { bv = ov; bi = oi; }
    }
    if (lane == 0) {
        int lo = 0, hi = H - 1;
        bool found = false;
        const long long rowv = (long long)row;
        while (lo <= hi) {
            int mid = (lo + hi) >> 1;
            long long v = g_hub64[mid];
            if (v == rowv) { found = true; break; }
            if (v < rowv) lo = mid + 1; else hi = mid - 1;
        }
        out[row] = found ? (float)rowv : (float)g_hub64[bi];
    }
}

static inline long isqrtl(long v) {
    long r = (long)(sqrt((double)v) + 0.5);
    while (r * r > v) r--;
    while ((r + 1) * (r + 1) <= v) r++;
    return r;
}

// ===========================================================================
extern "C" void kernel_launch(void* const* d_in, const int* in_sizes, int n_in,
                              void* d_out, int out_size)
{
    long sz[16];
    int ord[16];
    int n = n_in > 16 ? 16 : n_in;
    for (int i = 0; i < n; i++) { sz[i] = (long)(unsigned)in_sizes[i]; ord[i] = i; }
    for (int a = 0; a < n; a++)
        for (int b = a + 1; b < n; b++)
            if (sz[ord[b]] > sz[ord[a]]) { int t = ord[a]; ord[a] = ord[b]; ord[b] = t; }

    const int sX = ord[0];
    const int wA = ord[1], wB = ord[2];
    const int sH = ord[n - 1];
    const int bA = (n >= 6) ? ord[3] : ord[1];
    const int bB = (n >= 6) ? ord[4] : ord[2];

    long E = 0, N = 0;
    int  c32 = 0, c64 = 0, verdict_n = 0;
    {
        long Ee = isqrtl(sz[wA]);
        bool okE = (Ee > 0) && (Ee * Ee == sz[wA]) && (sz[wA] == sz[wB]) &&
                   (sz[bA] == Ee) && (sz[bB] == Ee) &&
                   (sz[sX] % Ee == 0) && (Ee % 32 == 0);
        if (okE) {
            E = Ee; N = sz[sX] / Ee;
            c32 = (int)sz[sH]; c64 = (int)sz[sH];
            verdict_n = (int)(sz[sH] / 2);
        } else {
            long Eb = isqrtl(sz[wA] / 4);
            bool okB = (Eb > 0) && (Eb * Eb * 4 == sz[wA]) && (sz[wA] == sz[wB]) &&
                       (sz[bA] == Eb * 4) && (sz[bB] == Eb * 4) &&
                       (sz[sX] % (Eb * 4) == 0) && (Eb % 32 == 0);
            if (okB) {
                E = Eb; N = sz[sX] / 4 / Eb;
                c32 = (int)(sz[sH] / 4); c64 = (int)(sz[sH] / 8);
                verdict_n = c64;
            } else {
                E = 4096; N = 16384;
                c32 = 256; c64 = 256; verdict_n = 128;
            }
        }
    }
    if (E > MAXE) E = MAXE;
    if (N > MAXN) N = MAXN;
    if (N > (long)out_size) N = (long)out_size;
    int H_max = c32 > c64 ? c32 : c64;
    if (H_max > MAXH) H_max = MAXH;
    if (c32 > MAXH) c32 = MAXH;
    if (c64 > MAXH) c64 = MAXH;

    const int wlo = wA < wB ? wA : wB, whi = wA < wB ? wB : wA;
    const int blo = bA < bB ? bA : bB, bhi = bA < bB ? bB : bA;
    const bool x_first = (sX < wlo);
    const float* X   = (const float*)d_in[sX];
    const void*  hub = d_in[sH];
    const float* Wq  = (const float*)d_in[x_first ? wlo : whi];
    const float* Wk  = (const float*)d_in[x_first ? whi : wlo];
    const float* bq  = (const float*)d_in[x_first ? blo : bhi];
    const float* bk  = (const float*)d_in[x_first ? bhi : blo];

    float *pK, *pM, *pc, *pS;
    cudaGetSymbolAddress((void**)&pK, g_K);
    cudaGetSymbolAddress((void**)&pM, g_M);
    cudaGetSymbolAddress((void**)&pc, g_c);
    cudaGetSymbolAddress((void**)&pS, g_scores);

    const int iE = (int)E, iN = (int)N;
    auto cdiv = [](int a, int b) { return (a + b - 1) / b; };

    // 0) probe + normalize
    probe_normalize_kernel<<<1, 256>>>(hub, c32, c64, verdict_n, N);

    // 1) K = X[hub] @ Wk^T + bk   [H,E]
    sgemm_db<64, 64, 32, 4, 4, true, true, true>
        <<<dim3(cdiv(iE, 64), cdiv(H_max, 64)), 256>>>(X, Wk, bk, pK, iE, -1, iE, iE);

    // 2) c[h] = bq . K[h]
    bias_c_kernel<<<H_max, 256>>>(bq, iE);

    // 3) M = K @ Wq               [H,E]
    sgemm_db<64, 64, 32, 4, 4, false, false, false>
        <<<dim3(cdiv(iE, 64), cdiv(H_max, 64)), 256>>>(pK, Wq, nullptr, pM, iE, -1, iE, iE);

    // 4+5) scores + argmax
    const bool fast_ok = (c32 == c64) && (H_max % 64 == 0) && (H_max >= 64) &&
                         (iE % 32 == 0) && (iN % 128 == 0);
    if (fast_ok) {
        mh_convert_kernel<<<2048, 256>>>(H_max, iE);
        score_bf16<<<dim3(H_max / 64, iN / 128), 256>>>(X, iE, H_max);
        argmax_rescore<<<cdiv(iN * 32, 256), 256>>>(X, pM, (float*)d_out, iE, iN);
    } else {
        sgemm_db<128, 128, 16, 8, 8, true, false, true>
            <<<dim3(cdiv(H_max, 128), cdiv(iN, 128)), 256>>>(X, pM, pc, pS, iE, iN, -1, -1);
        argmax_kernel<<<cdiv(iN * 32, 256), 256>>>((float*)d_out, iN);
    }
}

// round 16
// speedup vs baseline: 1.1502x; 1.0002x over previous
#include <cuda_runtime.h>
#include <cuda_fp16.h>
#include <math.h>
#include <stdint.h>

// Capacity bounds (total static scratch ~104 MB)
constexpr int  MAXH = 512;
constexpr int  MAXE = 8192;
constexpr long MAXN = 32768;

__device__ __align__(16) float g_K[(long)MAXH * MAXE];         // 16 MB
__device__ __align__(16) float g_M[(long)MAXH * MAXE];         // 16 MB
__device__ __align__(16) float g_c[MAXH];
__device__ __align__(16) float g_scores[MAXN * (long)MAXH];    // 64 MB
__device__ __align__(16) __half g_Mh[(long)MAXH * MAXE];       // 8 MB
__device__ int       g_is64;
__device__ int       g_H;
__device__ int       g_hub32[MAXH];
__device__ long long g_hub64[MAXH];

__device__ __forceinline__ __half2 u2h(uint32_t u) {
    return *reinterpret_cast<__half2*>(&u);
}
__device__ __forceinline__ uint32_t h2u(__half2 h) {
    return *reinterpret_cast<uint32_t*>(&h);
}

// ---------------------------------------------------------------------------
// Probe hub width by content and resolve H (validated R10+).
// ---------------------------------------------------------------------------
__global__ void probe_normalize_kernel(const void* __restrict__ hub_raw,
                                       int c32, int c64, int verdict_n, long NN)
{
    __shared__ int s_is64, s_H;
    if (threadIdx.x == 0) {
        const long long* p64 = (const long long*)hub_raw;
        bool ok = true, nz = false;
        long long prev = -1;
        for (int i = 0; i < verdict_n; i++) {
            long long v = p64[i];
            if (v != 0) nz = true;
            if (v < 0 || v >= NN || v < prev) { ok = false; break; }
            prev = v;
        }
        s_is64 = (ok && nz) ? 1 : 0;
        s_H    = s_is64 ? c64 : c32;
        if (s_H > MAXH) s_H = MAXH;
        g_is64 = s_is64;
        g_H    = s_H;
    }
    __syncthreads();
    for (int i = threadIdx.x; i < s_H; i += blockDim.x) {
        long long v = s_is64 ? ((const long long*)hub_raw)[i]
                             : (long long)((const int*)hub_raw)[i];
        g_hub32[i] = (int)v;
        g_hub64[i] = v;
    }
}

// ---------------------------------------------------------------------------
// fp32 SGEMM (validated R11/R14 structure) — stages 1/3 + fallback stage 4.
// ---------------------------------------------------------------------------
template<int BM, int BN, int BK, int TM, int TN, bool TRANSB, bool GATHER, bool BIAS>
__launch_bounds__((BM / TM) * (BN / TN))
__global__ void sgemm_db(const float* __restrict__ A,
                         const float* __restrict__ B,
                         const float* __restrict__ bias,
                         float*       __restrict__ C,
                         int Kdim, int Mt_p, int Nt_p, int Cs_p)
{
    constexpr int RT = BN / TN;
    constexpr int CT = BM / TM;
    constexpr int THREADS = RT * CT;
    constexpr int A_LD = (BM * BK) / (THREADS * 4);
    constexpr int B_LD = (BN * BK) / (THREADS * 4);
    static_assert(A_LD >= 1 && B_LD >= 1, "tile too small");

    const int Hdev = g_H;
    const int Mt = (Mt_p < 0) ? Hdev : Mt_p;
    const int Nt = (Nt_p < 0) ? Hdev : Nt_p;
    const int Cs = (Cs_p < 0) ? Hdev : Cs_p;

    __shared__ __align__(16) float As[2][BK][BM];
    __shared__ __align__(16) float Bs[2][BK][BN];

    const int tx = threadIdx.x;
    const int tn = tx % RT;
    const int tm = tx / RT;
    const int m0 = blockIdx.y * BM;
    const int n0 = blockIdx.x * BN;

    float4 aR[A_LD], bR[B_LD];
    const int kTiles = Kdim / BK;

    auto gld = [&](int k0) {
#pragma unroll
        for (int l = 0; l < A_LD; l++) {
            int slot = tx + l * THREADS;
            int m  = slot / (BK / 4);
            int kq = slot % (BK / 4);
            int mi = m0 + m; if (mi > Mt - 1) mi = Mt - 1;
            long row = GATHER ? (long)g_hub32[mi] : (long)mi;
            aR[l] = *reinterpret_cast<const float4*>(&A[row * (long)Kdim + k0 + kq * 4]);
        }
        if constexpr (TRANSB) {
#pragma unroll
            for (int l = 0; l < B_LD; l++) {
                int slot = tx + l * THREADS;
                int nn = slot / (BK / 4);
                int kq = slot % (BK / 4);
                int ni = n0 + nn; if (ni > Nt - 1) ni = Nt - 1;
                bR[l] = *reinterpret_cast<const float4*>(&B[(long)ni * Kdim + k0 + kq * 4]);
            }
        } else {
#pragma unroll
            for (int l = 0; l < B_LD; l++) {
                int slot = tx + l * THREADS;
                int k  = slot / (BN / 4);
                int nq = slot % (BN / 4);
                int nb = n0 + nq * 4;
                if (nb > Nt - 4) nb = (Nt >= 4) ? (Nt - 4) & ~3 : 0;
                bR[l] = *reinterpret_cast<const float4*>(&B[(long)(k0 + k) * Cs + nb]);
            }
        }
    };
    auto sts = [&](int buf) {
#pragma unroll
        for (int l = 0; l < A_LD; l++) {
            int slot = tx + l * THREADS;
            int m  = slot / (BK / 4);
            int kq = slot % (BK / 4);
            As[buf][kq * 4 + 0][m] = aR[l].x;
            As[buf][kq * 4 + 1][m] = aR[l].y;
            As[buf][kq * 4 + 2][m] = aR[l].z;
            As[buf][kq * 4 + 3][m] = aR[l].w;
        }
        if constexpr (TRANSB) {
#pragma unroll
            for (int l = 0; l < B_LD; l++) {
                int slot = tx + l * THREADS;
                int nn = slot / (BK / 4);
                int kq = slot % (BK / 4);
                Bs[buf][kq * 4 + 0][nn] = bR[l].x;
                Bs[buf][kq * 4 + 1][nn] = bR[l].y;
                Bs[buf][kq * 4 + 2][nn] = bR[l].z;
                Bs[buf][kq * 4 + 3][nn] = bR[l].w;
            }
        } else {
#pragma unroll
            for (int l = 0; l < B_LD; l++) {
                int slot = tx + l * THREADS;
                int k  = slot / (BN / 4);
                int nq = slot % (BN / 4);
                *reinterpret_cast<float4*>(&Bs[buf][k][nq * 4]) = bR[l];
            }
        }
    };

    float acc[TM][TN];
#pragma unroll
    for (int j = 0; j < TM; j++)
#pragma unroll
        for (int i = 0; i < TN; i++) acc[j][i] = 0.f;

    gld(0); sts(0); __syncthreads();
    int cur = 0;
    for (int kt = 0; kt < kTiles; kt++) {
        if (kt + 1 < kTiles) gld((kt + 1) * BK);
#pragma unroll
        for (int kk = 0; kk < BK; kk++) {
            float ra[TM], rb[TN];
#pragma unroll
            for (int j = 0; j < TM; j += 4)
                *reinterpret_cast<float4*>(&ra[j]) =
                    *reinterpret_cast<const float4*>(&As[cur][kk][tm * TM + j]);
#pragma unroll
            for (int i = 0; i < TN; i += 4)
                *reinterpret_cast<float4*>(&rb[i]) =
                    *reinterpret_cast<const float4*>(&Bs[cur][kk][tn * TN + i]);
#pragma unroll
            for (int j = 0; j < TM; j++)
#pragma unroll
                for (int i = 0; i < TN; i++)
                    acc[j][i] = fmaf(ra[j], rb[i], acc[j][i]);
        }
        if (kt + 1 < kTiles) { sts(1 - cur); __syncthreads(); cur ^= 1; }
    }
#pragma unroll
    for (int j = 0; j < TM; j++) {
        int m = m0 + tm * TM + j;
        if (m >= Mt) continue;
#pragma unroll
        for (int i = 0; i < TN; i++) {
            int n = n0 + tn * TN + i;
            if (n >= Nt) continue;
            float v = acc[j][i];
            if constexpr (BIAS) v += bias[n];
            C[(long)m * Cs + n] = v;
        }
    }
}

// ---------------------------------------------------------------------------
__global__ void bias_c_kernel(const float* __restrict__ bq, int E)
{
    const int h = blockIdx.x;
    if (h >= g_H) return;
    __shared__ float red[256];
    float s = 0.f;
    for (int e = threadIdx.x; e < E; e += 256)
        s = fmaf(bq[e], g_K[(long)h * E + e], s);
    red[threadIdx.x] = s;
    __syncthreads();
    for (int off = 128; off > 0; off >>= 1) {
        if (threadIdx.x < off) red[threadIdx.x] += red[threadIdx.x + off];
        __syncthreads();
    }
    if (threadIdx.x == 0) g_c[h] = red[0];
}

// M -> fp16 (single rounding; |M| ~ O(10) << 65504, safe)
__global__ void mh_convert_kernel(int H, int E)
{
    const long total = (long)H * E;
    for (long i = (long)blockIdx.x * blockDim.x + threadIdx.x;
         i < total; i += (long)gridDim.x * blockDim.x)
        g_Mh[i] = __float2half_rn(g_M[i]);
}

// ===========================================================================
// Approximate scores via fp16 HFMA2 (native dual-lane): BM=128 rows x BN=64
// hubs, 32 K per tile packed as 16 half2 pairs. Chunk accumulators in half2,
// flushed to fp32 per tile. Writes s_approx + c into g_scores.
// Requires E%32==0, N%128==0, H%64==0.
// ===========================================================================
__global__ __launch_bounds__(256)
void score_fp16(const float* __restrict__ X, int E, int H)
{
    constexpr int BM = 128, BN = 64, BKP = 16;
    __shared__ __align__(16) uint32_t As[2][BKP][BM];
    __shared__ __align__(16) uint32_t Bs[2][BKP][BN];

    const int tx = threadIdx.x;
    const int tn = tx & 15;          // 16 groups -> TN=4
    const int tm = tx >> 4;          // 16 groups -> TM=8
    const int r0 = blockIdx.y * BM;
    const int n0 = blockIdx.x * BN;

    float4 aR[4];
    uint4  bRv;
    const int tiles = E / 32;

    auto gld = [&](int k0) {
#pragma unroll
        for (int l = 0; l < 4; l++) {
            int slot = tx + l * 256;
            int m = slot >> 3;
            int q = slot & 7;
            aR[l] = *reinterpret_cast<const float4*>(&X[(long)(r0 + m) * E + k0 + q * 4]);
        }
        {
            int h = tx >> 2;
            int q = tx & 3;
            bRv = *reinterpret_cast<const uint4*>(&g_Mh[(long)(n0 + h) * E + k0 + q * 8]);
        }
    };
    auto sts = [&](int buf) {
#pragma unroll
        for (int l = 0; l < 4; l++) {
            int slot = tx + l * 256;
            int m = slot >> 3;
            int q = slot & 7;
            As[buf][2 * q + 0][m] = h2u(__float22half2_rn(make_float2(aR[l].x, aR[l].y)));
            As[buf][2 * q + 1][m] = h2u(__float22half2_rn(make_float2(aR[l].z, aR[l].w)));
        }
        {
            int h = tx >> 2;
            int q = tx & 3;
            Bs[buf][4 * q + 0][h] = bRv.x;
            Bs[buf][4 * q + 1][h] = bRv.y;
            Bs[buf][4 * q + 2][h] = bRv.z;
            Bs[buf][4 * q + 3][h] = bRv.w;
        }
    };

    float accf[8][4];
#pragma unroll
    for (int j = 0; j < 8; j++)
#pragma unroll
        for (int i = 0; i < 4; i++) accf[j][i] = 0.f;

    gld(0); sts(0); __syncthreads();
    int cur = 0;
    const __half2 z2 = __float2half2_rn(0.f);

    for (int t = 0; t < tiles; t++) {
        if (t + 1 < tiles) gld((t + 1) * 32);

        __half2 acc2[8][4];
#pragma unroll
        for (int j = 0; j < 8; j++)
#pragma unroll
            for (int i = 0; i < 4; i++) acc2[j][i] = z2;

#pragma unroll
        for (int kp = 0; kp < BKP; kp++) {
            uint32_t ra[8], rb[4];
            *reinterpret_cast<uint4*>(&ra[0]) =
                *reinterpret_cast<const uint4*>(&As[cur][kp][tm * 8]);
            *reinterpret_cast<uint4*>(&ra[4]) =
                *reinterpret_cast<const uint4*>(&As[cur][kp][tm * 8 + 4]);
            *reinterpret_cast<uint4*>(&rb[0]) =
                *reinterpret_cast<const uint4*>(&Bs[cur][kp][tn * 4]);
#pragma unroll
            for (int j = 0; j < 8; j++)
#pragma unroll
                for (int i = 0; i < 4; i++)
                    acc2[j][i] = __hfma2(u2h(ra[j]), u2h(rb[i]), acc2[j][i]);
        }
        // flush chunk to fp32
#pragma unroll
        for (int j = 0; j < 8; j++)
#pragma unroll
            for (int i = 0; i < 4; i++) {
                float2 f = __half22float2(acc2[j][i]);
                accf[j][i] += f.x + f.y;
            }

        if (t + 1 < tiles) { sts(1 - cur); __syncthreads(); cur ^= 1; }
    }

#pragma unroll
    for (int j = 0; j < 8; j++) {
        const int m = r0 + tm * 8 + j;
#pragma unroll
        for (int i = 0; i < 4; i++) {
            const int h = n0 + tn * 4 + i;
            g_scores[(long)m * H + h] = accf[j][i] + g_c[h];
        }
    }
}

// ===========================================================================
// Argmax with exact rescoring of near-ties (validated R15). fp16 scores ->
// sigma_e ~8x smaller than bf16; delta widened to 0.15*row-sigma for seed
// robustness.
// ===========================================================================
__global__ void argmax_rescore(const float* __restrict__ X,
                               const float* __restrict__ Mx,
                               float* __restrict__ out, int E, int N)
{
    const int gtid = blockIdx.x * blockDim.x + threadIdx.x;
    const int row  = gtid >> 5;
    const int lane = gtid & 31;
    if (row >= N) return;

    const int H = g_H;
    const float* s = g_scores + (long)row * H;

    float bv = -INFINITY; int bi = 0;
    float sum = 0.f, sum2 = 0.f;
    for (int h = lane; h < H; h += 32) {
        float v = s[h];
        sum += v; sum2 += v * v;
        if (v > bv) { bv = v; bi = h; }
    }
#pragma unroll
    for (int off = 16; off > 0; off >>= 1) {
        float ov = __shfl_xor_sync(0xffffffffu, bv, off);
        int   oi = __shfl_xor_sync(0xffffffffu, bi, off);
        if (ov > bv || (ov == bv && oi < bi)) { bv = ov; bi = oi; }
        sum  += __shfl_xor_sync(0xffffffffu, sum,  off);
        sum2 += __shfl_xor_sync(0xffffffffu, sum2, off);
    }
    const float mean = sum / H;
    const float var  = fmaxf(sum2 / H - mean * mean, 0.f);
    const float delta = 0.15f * sqrtf(var) + 1e-20f;
    const float thr = bv - delta;

    int cnt = 0;
    for (int h = lane; h < H; h += 32)
        if (s[h] >= thr) cnt++;
#pragma unroll
    for (int off = 16; off > 0; off >>= 1)
        cnt += __shfl_xor_sync(0xffffffffu, cnt, off);

    int pick = bi;
    if (cnt > 1) {
        float bestE = -INFINITY; int bestH = 0;
        for (int h = 0; h < H; h++) {
            if (s[h] < thr) continue;              // uniform across warp
            float part = 0.f;
            const float* xr = X  + (long)row * E;
            const float* mr = Mx + (long)h   * E;
            for (int e = lane * 4; e < E; e += 128) {
                float4 xv = *reinterpret_cast<const float4*>(&xr[e]);
                float4 mv = *reinterpret_cast<const float4*>(&mr[e]);
                part = fmaf(xv.x, mv.x, part);
                part = fmaf(xv.y, mv.y, part);
                part = fmaf(xv.z, mv.z, part);
                part = fmaf(xv.w, mv.w, part);
            }
#pragma unroll
            for (int off = 16; off > 0; off >>= 1)
                part += __shfl_xor_sync(0xffffffffu, part, off);
            float ex = part + g_c[h];
            if (ex > bestE) { bestE = ex; bestH = h; }   // first-wins in h
        }
        pick = bestH;
    }

    if (lane == 0) {
        int lo = 0, hi = H - 1;
        bool found = false;
        const long long rowv = (long long)row;
        while (lo <= hi) {
            int mid = (lo + hi) >> 1;
            long long v = g_hub64[mid];
            if (v == rowv) { found = true; break; }
            if (v < rowv) lo = mid + 1; else hi = mid - 1;
        }
        out[row] = found ? (float)rowv : (float)g_hub64[pick];
    }
}

// ---------------- fallback SIMT argmax (validated) -------------------------
__global__ void argmax_kernel(float* __restrict__ out, int N)
{
    const int gtid = blockIdx.x * blockDim.x + threadIdx.x;
    const int row  = gtid >> 5;
    const int lane = gtid & 31;
    if (row >= N) return;
    const int H = g_H;
    const float* s = g_scores + (long)row * H;
    float bv = -INFINITY;
    int   bi = 0;
    for (int h = lane; h < H; h += 32) {
        float v = s[h];
        if (v > bv) { bv = v; bi = h; }
    }
#pragma unroll
    for (int off = 16; off > 0; off >>= 1) {
        float ov = __shfl_down_sync(0xffffffffu, bv, off);
        int   oi = __shfl_down_sync(0xffffffffu, bi, off);
        if (ov > bv || (ov == bv && oi < bi)) { bv = ov; bi = oi; }
    }
    if (lane == 0) {
        int lo = 0, hi = H - 1;
        bool found = false;
        const long long rowv = (long long)row;
        while (lo <= hi) {
            int mid = (lo + hi) >> 1;
            long long v = g_hub64[mid];
            if (v == rowv) { found = true; break; }
            if (v < rowv) lo = mid + 1; else hi = mid - 1;
        }
        out[row] = found ? (float)rowv : (float)g_hub64[bi];
    }
}

static inline long isqrtl(long v) {
    long r = (long)(sqrt((double)v) + 0.5);
    while (r * r > v) r--;
    while ((r + 1) * (r + 1) <= v) r++;
    return r;
}

// ===========================================================================
extern "C" void kernel_launch(void* const* d_in, const int* in_sizes, int n_in,
                              void* d_out, int out_size)
{
    long sz[16];
    int ord[16];
    int n = n_in > 16 ? 16 : n_in;
    for (int i = 0; i < n; i++) { sz[i] = (long)(unsigned)in_sizes[i]; ord[i] = i; }
    for (int a = 0; a < n; a++)
        for (int b = a + 1; b < n; b++)
            if (sz[ord[b]] > sz[ord[a]]) { int t = ord[a]; ord[a] = ord[b]; ord[b] = t; }

    const int sX = ord[0];
    const int wA = ord[1], wB = ord[2];
    const int sH = ord[n - 1];
    const int bA = (n >= 6) ? ord[3] : ord[1];
    const int bB = (n >= 6) ? ord[4] : ord[2];

    long E = 0, N = 0;
    int  c32 = 0, c64 = 0, verdict_n = 0;
    {
        long Ee = isqrtl(sz[wA]);
        bool okE = (Ee > 0) && (Ee * Ee == sz[wA]) && (sz[wA] == sz[wB]) &&
                   (sz[bA] == Ee) && (sz[bB] == Ee) &&
                   (sz[sX] % Ee == 0) && (Ee % 32 == 0);
        if (okE) {
            E = Ee; N = sz[sX] / Ee;
            c32 = (int)sz[sH]; c64 = (int)sz[sH];
            verdict_n = (int)(sz[sH] / 2);
        } else {
            long Eb = isqrtl(sz[wA] / 4);
            bool okB = (Eb > 0) && (Eb * Eb * 4 == sz[wA]) && (sz[wA] == sz[wB]) &&
                       (sz[bA] == Eb * 4) && (sz[bB] == Eb * 4) &&
                       (sz[sX] % (Eb * 4) == 0) && (Eb % 32 == 0);
            if (okB) {
                E = Eb; N = sz[sX] / 4 / Eb;
                c32 = (int)(sz[sH] / 4); c64 = (int)(sz[sH] / 8);
                verdict_n = c64;
            } else {
                E = 4096; N = 16384;
                c32 = 256; c64 = 256; verdict_n = 128;
            }
        }
    }
    if (E > MAXE) E = MAXE;
    if (N > MAXN) N = MAXN;
    if (N > (long)out_size) N = (long)out_size;
    int H_max = c32 > c64 ? c32 : c64;
    if (H_max > MAXH) H_max = MAXH;
    if (c32 > MAXH) c32 = MAXH;
    if (c64 > MAXH) c64 = MAXH;

    const int wlo = wA < wB ? wA : wB, whi = wA < wB ? wB : wA;
    const int blo = bA < bB ? bA : bB, bhi = bA < bB ? bB : bA;
    const bool x_first = (sX < wlo);
    const float* X   = (const float*)d_in[sX];
    const void*  hub = d_in[sH];
    const float* Wq  = (const float*)d_in[x_first ? wlo : whi];
    const float* Wk  = (const float*)d_in[x_first ? whi : wlo];
    const float* bq  = (const float*)d_in[x_first ? blo : bhi];
    const float* bk  = (const float*)d_in[x_first ? bhi : blo];

    float *pK, *pM, *pc, *pS;
    cudaGetSymbolAddress((void**)&pK, g_K);
    cudaGetSymbolAddress((void**)&pM, g_M);
    cudaGetSymbolAddress((void**)&pc, g_c);
    cudaGetSymbolAddress((void**)&pS, g_scores);

    const int iE = (int)E, iN = (int)N;
    auto cdiv = [](int a, int b) { return (a + b - 1) / b; };

    // 0) probe + normalize
    probe_normalize_kernel<<<1, 256>>>(hub, c32, c64, verdict_n, N);

    // 1) K = X[hub] @ Wk^T + bk   [H,E]
    sgemm_db<64, 64, 32, 4, 4, true, true, true>
        <<<dim3(cdiv(iE, 64), cdiv(H_max, 64)), 256>>>(X, Wk, bk, pK, iE, -1, iE, iE);

    // 2) c[h] = bq . K[h]
    bias_c_kernel<<<H_max, 256>>>(bq, iE);

    // 3) M = K @ Wq               [H,E]
    sgemm_db<64, 64, 32, 4, 4, false, false, false>
        <<<dim3(cdiv(iE, 64), cdiv(H_max, 64)), 256>>>(pK, Wq, nullptr, pM, iE, -1, iE, iE);

    // 4+5) scores + argmax
    const bool fast_ok = (c32 == c64) && (H_max % 64 == 0) && (H_max >= 64) &&
                         (iE % 32 == 0) && (iN % 128 == 0);
    if (fast_ok) {
        mh_convert_kernel<<<2048, 256>>>(H_max, iE);
        score_fp16<<<dim3(H_max / 64, iN / 128), 256>>>(X, iE, H_max);
        argmax_rescore<<<cdiv(iN * 32, 256), 256>>>(X, pM, (float*)d_out, iE, iN);
    } else {
        sgemm_db<128, 128, 16, 8, 8, true, false, true>
            <<<dim3(cdiv(H_max, 128), cdiv(iN, 128)), 256>>>(X, pM, pc, pS, iE, iN, -1, -1);
        argmax_kernel<<<cdiv(iN * 32, 256), 256>>>((float*)d_out, iN);
    }
}

// round 17
// speedup vs baseline: 1.6548x; 1.4387x over previous
#include <cuda_runtime.h>
#include <cuda_fp16.h>
#include <math.h>
#include <stdint.h>

// Capacity bounds (total static scratch ~104 MB)
constexpr int  MAXH = 512;
constexpr int  MAXE = 8192;
constexpr long MAXN = 32768;

__device__ __align__(16) float g_K[(long)MAXH * MAXE];         // 16 MB
__device__ __align__(16) float g_M[(long)MAXH * MAXE];         // 16 MB
__device__ __align__(16) float g_c[MAXH];
__device__ __align__(16) float g_scores[MAXN * (long)MAXH];    // 64 MB
__device__ __align__(16) __half g_Mh[(long)MAXH * MAXE];       // 8 MB
__device__ int       g_is64;
__device__ int       g_H;
__device__ int       g_hub32[MAXH];
__device__ long long g_hub64[MAXH];

// ---------------------------------------------------------------------------
// Probe hub width by content and resolve H (validated R10+).
// ---------------------------------------------------------------------------
__global__ void probe_normalize_kernel(const void* __restrict__ hub_raw,
                                       int c32, int c64, int verdict_n, long NN)
{
    __shared__ int s_is64, s_H;
    if (threadIdx.x == 0) {
        const long long* p64 = (const long long*)hub_raw;
        bool ok = true, nz = false;
        long long prev = -1;
        for (int i = 0; i < verdict_n; i++) {
            long long v = p64[i];
            if (v != 0) nz = true;
            if (v < 0 || v >= NN || v < prev) { ok = false; break; }
            prev = v;
        }
        s_is64 = (ok && nz) ? 1 : 0;
        s_H    = s_is64 ? c64 : c32;
        if (s_H > MAXH) s_H = MAXH;
        g_is64 = s_is64;
        g_H    = s_H;
    }
    __syncthreads();
    for (int i = threadIdx.x; i < s_H; i += blockDim.x) {
        long long v = s_is64 ? ((const long long*)hub_raw)[i]
                             : (long long)((const int*)hub_raw)[i];
        g_hub32[i] = (int)v;
        g_hub64[i] = v;
    }
}

// ---------------------------------------------------------------------------
// fp32 SGEMM (validated R11/R14 structure) — stages 1/3 + fallback stage 4.
// ---------------------------------------------------------------------------
template<int BM, int BN, int BK, int TM, int TN, bool TRANSB, bool GATHER, bool BIAS>
__launch_bounds__((BM / TM) * (BN / TN))
__global__ void sgemm_db(const float* __restrict__ A,
                         const float* __restrict__ B,
                         const float* __restrict__ bias,
                         float*       __restrict__ C,
                         int Kdim, int Mt_p, int Nt_p, int Cs_p)
{
    constexpr int RT = BN / TN;
    constexpr int CT = BM / TM;
    constexpr int THREADS = RT * CT;
    constexpr int A_LD = (BM * BK) / (THREADS * 4);
    constexpr int B_LD = (BN * BK) / (THREADS * 4);
    static_assert(A_LD >= 1 && B_LD >= 1, "tile too small");

    const int Hdev = g_H;
    const int Mt = (Mt_p < 0) ? Hdev : Mt_p;
    const int Nt = (Nt_p < 0) ? Hdev : Nt_p;
    const int Cs = (Cs_p < 0) ? Hdev : Cs_p;

    __shared__ __align__(16) float As[2][BK][BM];
    __shared__ __align__(16) float Bs[2][BK][BN];

    const int tx = threadIdx.x;
    const int tn = tx % RT;
    const int tm = tx / RT;
    const int m0 = blockIdx.y * BM;
    const int n0 = blockIdx.x * BN;

    float4 aR[A_LD], bR[B_LD];
    const int kTiles = Kdim / BK;

    auto gld = [&](int k0) {
#pragma unroll
        for (int l = 0; l < A_LD; l++) {
            int slot = tx + l * THREADS;
            int m  = slot / (BK / 4);
            int kq = slot % (BK / 4);
            int mi = m0 + m; if (mi > Mt - 1) mi = Mt - 1;
            long row = GATHER ? (long)g_hub32[mi] : (long)mi;
            aR[l] = *reinterpret_cast<const float4*>(&A[row * (long)Kdim + k0 + kq * 4]);
        }
        if constexpr (TRANSB) {
#pragma unroll
            for (int l = 0; l < B_LD; l++) {
                int slot = tx + l * THREADS;
                int nn = slot / (BK / 4);
                int kq = slot % (BK / 4);
                int ni = n0 + nn; if (ni > Nt - 1) ni = Nt - 1;
                bR[l] = *reinterpret_cast<const float4*>(&B[(long)ni * Kdim + k0 + kq * 4]);
            }
        } else {
#pragma unroll
            for (int l = 0; l < B_LD; l++) {
                int slot = tx + l * THREADS;
                int k  = slot / (BN / 4);
                int nq = slot % (BN / 4);
                int nb = n0 + nq * 4;
                if (nb > Nt - 4) nb = (Nt >= 4) ? (Nt - 4) & ~3 : 0;
                bR[l] = *reinterpret_cast<const float4*>(&B[(long)(k0 + k) * Cs + nb]);
            }
        }
    };
    auto sts = [&](int buf) {
#pragma unroll
        for (int l = 0; l < A_LD; l++) {
            int slot = tx + l * THREADS;
            int m  = slot / (BK / 4);
            int kq = slot % (BK / 4);
            As[buf][kq * 4 + 0][m] = aR[l].x;
            As[buf][kq * 4 + 1][m] = aR[l].y;
            As[buf][kq * 4 + 2][m] = aR[l].z;
            As[buf][kq * 4 + 3][m] = aR[l].w;
        }
        if constexpr (TRANSB) {
#pragma unroll
            for (int l = 0; l < B_LD; l++) {
                int slot = tx + l * THREADS;
                int nn = slot / (BK / 4);
                int kq = slot % (BK / 4);
                Bs[buf][kq * 4 + 0][nn] = bR[l].x;
                Bs[buf][kq * 4 + 1][nn] = bR[l].y;
                Bs[buf][kq * 4 + 2][nn] = bR[l].z;
                Bs[buf][kq * 4 + 3][nn] = bR[l].w;
            }
        } else {
#pragma unroll
            for (int l = 0; l < B_LD; l++) {
                int slot = tx + l * THREADS;
                int k  = slot / (BN / 4);
                int nq = slot % (BN / 4);
                *reinterpret_cast<float4*>(&Bs[buf][k][nq * 4]) = bR[l];
            }
        }
    };

    float acc[TM][TN];
#pragma unroll
    for (int j = 0; j < TM; j++)
#pragma unroll
        for (int i = 0; i < TN; i++) acc[j][i] = 0.f;

    gld(0); sts(0); __syncthreads();
    int cur = 0;
    for (int kt = 0; kt < kTiles; kt++) {
        if (kt + 1 < kTiles) gld((kt + 1) * BK);
#pragma unroll
        for (int kk = 0; kk < BK; kk++) {
            float ra[TM], rb[TN];
#pragma unroll
            for (int j = 0; j < TM; j += 4)
                *reinterpret_cast<float4*>(&ra[j]) =
                    *reinterpret_cast<const float4*>(&As[cur][kk][tm * TM + j]);
#pragma unroll
            for (int i = 0; i < TN; i += 4)
                *reinterpret_cast<float4*>(&rb[i]) =
                    *reinterpret_cast<const float4*>(&Bs[cur][kk][tn * TN + i]);
#pragma unroll
            for (int j = 0; j < TM; j++)
#pragma unroll
                for (int i = 0; i < TN; i++)
                    acc[j][i] = fmaf(ra[j], rb[i], acc[j][i]);
        }
        if (kt + 1 < kTiles) { sts(1 - cur); __syncthreads(); cur ^= 1; }
    }
#pragma unroll
    for (int j = 0; j < TM; j++) {
        int m = m0 + tm * TM + j;
        if (m >= Mt) continue;
#pragma unroll
        for (int i = 0; i < TN; i++) {
            int n = n0 + tn * TN + i;
            if (n >= Nt) continue;
            float v = acc[j][i];
            if constexpr (BIAS) v += bias[n];
            C[(long)m * Cs + n] = v;
        }
    }
}

// ---------------------------------------------------------------------------
__global__ void bias_c_kernel(const float* __restrict__ bq, int E)
{
    const int h = blockIdx.x;
    if (h >= g_H) return;
    __shared__ float red[256];
    float s = 0.f;
    for (int e = threadIdx.x; e < E; e += 256)
        s = fmaf(bq[e], g_K[(long)h * E + e], s);
    red[threadIdx.x] = s;
    __syncthreads();
    for (int off = 128; off > 0; off >>= 1) {
        if (threadIdx.x < off) red[threadIdx.x] += red[threadIdx.x + off];
        __syncthreads();
    }
    if (threadIdx.x == 0) g_c[h] = red[0];
}

// M -> fp16 (single rounding; |M| ~ O(10) << 65504, safe)
__global__ void mh_convert_kernel(int H, int E)
{
    const long total = (long)H * E;
    for (long i = (long)blockIdx.x * blockDim.x + threadIdx.x;
         i < total; i += (long)gridDim.x * blockDim.x)
        g_Mh[i] = __float2half_rn(g_M[i]);
}

// ===========================================================================
// Approximate scores via HMMA mma.sync (fp16 in, FP32 ACCUMULATE — base PTX,
// no 'a' features). BM=128 rows x BN=64 hubs x BK=32. 8 warps, warp grid
// 2(M)x4(N), warp tile 64x16 = 4 M-frags x 2 N-frags of m16n8k16.
// Fragments read directly from padded smem (PAD=40 halves -> conflict-free).
// Requires E%32==0, N%128==0, H%64==0.
// ===========================================================================
__global__ __launch_bounds__(256)
void score_mma(const float* __restrict__ X, int E, int H)
{
    constexpr int BM = 128, BN = 64, BK = 32, PAD = 40;
    __shared__ __align__(16) __half As[2][BM][PAD];
    __shared__ __align__(16) __half Bs[2][BN][PAD];
    __shared__ float cS[BN];

    const int tx   = threadIdx.x;
    const int wid  = tx >> 5;
    const int lane = tx & 31;
    const int r0 = blockIdx.y * BM;
    const int n0 = blockIdx.x * BN;
    const int wm = wid & 1;            // 2 along M
    const int wn = wid >> 1;           // 4 along N
    const int mbase = wm * 64;
    const int nbase = wn * 16;
    const int row0 = lane >> 2;        // groupID
    const int qt   = lane & 3;         // threadID in group

    for (int i = tx; i < BN; i += 256) cS[i] = g_c[n0 + i];

    float acc[4][2][4];
#pragma unroll
    for (int mi = 0; mi < 4; mi++)
#pragma unroll
        for (int ni = 0; ni < 2; ni++)
#pragma unroll
            for (int c = 0; c < 4; c++) acc[mi][ni][c] = 0.f;

    const int tiles = E / BK;
    float4 aR[4];
    uint4  bRv;
    const int arow = tx >> 1, ahalf = tx & 1;     // A: 2 threads per row
    const int brow = tx >> 2, bchk  = tx & 3;     // B: 4 chunks per row

    auto gld = [&](int k0) {
        const float* src = X + (long)(r0 + arow) * E + k0 + ahalf * 16;
#pragma unroll
        for (int q = 0; q < 4; q++)
            aR[q] = reinterpret_cast<const float4*>(src)[q];
        bRv = *reinterpret_cast<const uint4*>(&g_Mh[(long)(n0 + brow) * E + k0 + bchk * 8]);
    };
    auto sts = [&](int buf) {
#pragma unroll
        for (int q = 0; q < 4; q++) {
            __half2 h0 = __float22half2_rn(make_float2(aR[q].x, aR[q].y));
            __half2 h1 = __float22half2_rn(make_float2(aR[q].z, aR[q].w));
            *reinterpret_cast<uint32_t*>(&As[buf][arow][ahalf * 16 + q * 4])     =
                *reinterpret_cast<uint32_t*>(&h0);
            *reinterpret_cast<uint32_t*>(&As[buf][arow][ahalf * 16 + q * 4 + 2]) =
                *reinterpret_cast<uint32_t*>(&h1);
        }
        *reinterpret_cast<uint4*>(&Bs[buf][brow][bchk * 8]) = bRv;
    };

    gld(0); sts(0); __syncthreads();
    int cur = 0;
    for (int t = 0; t < tiles; t++) {
        if (t + 1 < tiles) gld((t + 1) * BK);

#pragma unroll
        for (int ks = 0; ks < BK; ks += 16) {
            uint32_t bf[2][2];
#pragma unroll
            for (int ni = 0; ni < 2; ni++) {
                const __half* bp = &Bs[cur][nbase + ni * 8 + row0][ks + 2 * qt];
                bf[ni][0] = *reinterpret_cast<const uint32_t*>(bp);
                bf[ni][1] = *reinterpret_cast<const uint32_t*>(bp + 8);
            }
#pragma unroll
            for (int mi = 0; mi < 4; mi++) {
                const __half* ap0 = &As[cur][mbase + mi * 16 + row0][ks + 2 * qt];
                const __half* ap1 = &As[cur][mbase + mi * 16 + row0 + 8][ks + 2 * qt];
                uint32_t a0 = *reinterpret_cast<const uint32_t*>(ap0);
                uint32_t a1 = *reinterpret_cast<const uint32_t*>(ap1);
                uint32_t a2 = *reinterpret_cast<const uint32_t*>(ap0 + 8);
                uint32_t a3 = *reinterpret_cast<const uint32_t*>(ap1 + 8);
#pragma unroll
                for (int ni = 0; ni < 2; ni++) {
                    asm volatile(
                        "mma.sync.aligned.m16n8k16.row.col.f32.f16.f16.f32 "
                        "{%0,%1,%2,%3}, {%4,%5,%6,%7}, {%8,%9}, {%0,%1,%2,%3};"
                        : "+f"(acc[mi][ni][0]), "+f"(acc[mi][ni][1]),
                          "+f"(acc[mi][ni][2]), "+f"(acc[mi][ni][3])
                        : "r"(a0), "r"(a1), "r"(a2), "r"(a3),
                          "r"(bf[ni][0]), "r"(bf[ni][1]));
                }
            }
        }

        if (t + 1 < tiles) { sts(1 - cur); __syncthreads(); cur ^= 1; }
    }

    // epilogue: c0=C[row0][2t], c1=C[row0][2t+1], c2=C[row0+8][2t], c3=...
#pragma unroll
    for (int mi = 0; mi < 4; mi++) {
#pragma unroll
        for (int ni = 0; ni < 2; ni++) {
            const int col = nbase + ni * 8 + 2 * qt;
            const int rA  = r0 + mbase + mi * 16 + row0;
            const int rB  = rA + 8;
            g_scores[(long)rA * H + n0 + col]     = acc[mi][ni][0] + cS[col];
            g_scores[(long)rA * H + n0 + col + 1] = acc[mi][ni][1] + cS[col + 1];
            g_scores[(long)rB * H + n0 + col]     = acc[mi][ni][2] + cS[col];
            g_scores[(long)rB * H + n0 + col + 1] = acc[mi][ni][3] + cS[col + 1];
        }
    }
}

// ===========================================================================
// Argmax with exact rescoring of near-ties (validated R15/R16).
// ===========================================================================
__global__ void argmax_rescore(const float* __restrict__ X,
                               const float* __restrict__ Mx,
                               float* __restrict__ out, int E, int N)
{
    const int gtid = blockIdx.x * blockDim.x + threadIdx.x;
    const int row  = gtid >> 5;
    const int lane = gtid & 31;
    if (row >= N) return;

    const int H = g_H;
    const float* s = g_scores + (long)row * H;

    float bv = -INFINITY; int bi = 0;
    float sum = 0.f, sum2 = 0.f;
    for (int h = lane; h < H; h += 32) {
        float v = s[h];
        sum += v; sum2 += v * v;
        if (v > bv) { bv = v; bi = h; }
    }
#pragma unroll
    for (int off = 16; off > 0; off >>= 1) {
        float ov = __shfl_xor_sync(0xffffffffu, bv, off);
        int   oi = __shfl_xor_sync(0xffffffffu, bi, off);
        if (ov > bv || (ov == bv && oi < bi)) { bv = ov; bi = oi; }
        sum  += __shfl_xor_sync(0xffffffffu, sum,  off);
        sum2 += __shfl_xor_sync(0xffffffffu, sum2, off);
    }
    const float mean = sum / H;
    const float var  = fmaxf(sum2 / H - mean * mean, 0.f);
    const float delta = 0.15f * sqrtf(var) + 1e-20f;
    const float thr = bv - delta;

    int cnt = 0;
    for (int h = lane; h < H; h += 32)
        if (s[h] >= thr) cnt++;
#pragma unroll
    for (int off = 16; off > 0; off >>= 1)
        cnt += __shfl_xor_sync(0xffffffffu, cnt, off);

    int pick = bi;
    if (cnt > 1) {
        float bestE = -INFINITY; int bestH = 0;
        for (int h = 0; h < H; h++) {
            if (s[h] < thr) continue;              // uniform across warp
            float part = 0.f;
            const float* xr = X  + (long)row * E;
            const float* mr = Mx + (long)h   * E;
            for (int e = lane * 4; e < E; e += 128) {
                float4 xv = *reinterpret_cast<const float4*>(&xr[e]);
                float4 mv = *reinterpret_cast<const float4*>(&mr[e]);
                part = fmaf(xv.x, mv.x, part);
                part = fmaf(xv.y, mv.y, part);
                part = fmaf(xv.z, mv.z, part);
                part = fmaf(xv.w, mv.w, part);
            }
#pragma unroll
            for (int off = 16; off > 0; off >>= 1)
                part += __shfl_xor_sync(0xffffffffu, part, off);
            float ex = part + g_c[h];
            if (ex > bestE) { bestE = ex; bestH = h; }   // first-wins in h
        }
        pick = bestH;
    }

    if (lane == 0) {
        int lo = 0, hi = H - 1;
        bool found = false;
        const long long rowv = (long long)row;
        while (lo <= hi) {
            int mid = (lo + hi) >> 1;
            long long v = g_hub64[mid];
            if (v == rowv) { found = true; break; }
            if (v < rowv) lo = mid + 1; else hi = mid - 1;
        }
        out[row] = found ? (float)rowv : (float)g_hub64[pick];
    }
}

// ---------------- fallback SIMT argmax (validated) -------------------------
__global__ void argmax_kernel(float* __restrict__ out, int N)
{
    const int gtid = blockIdx.x * blockDim.x + threadIdx.x;
    const int row  = gtid >> 5;
    const int lane = gtid & 31;
    if (row >= N) return;
    const int H = g_H;
    const float* s = g_scores + (long)row * H;
    float bv = -INFINITY;
    int   bi = 0;
    for (int h = lane; h < H; h += 32) {
        float v = s[h];
        if (v > bv) { bv = v; bi = h; }
    }
#pragma unroll
    for (int off = 16; off > 0; off >>= 1) {
        float ov = __shfl_down_sync(0xffffffffu, bv, off);
        int   oi = __shfl_down_sync(0xffffffffu, bi, off);
        if (ov > bv || (ov == bv && oi < bi)) { bv = ov; bi = oi; }
    }
    if (lane == 0) {
        int lo = 0, hi = H - 1;
        bool found = false;
        const long long rowv = (long long)row;
        while (lo <= hi) {
            int mid = (lo + hi) >> 1;
            long long v = g_hub64[mid];
            if (v == rowv) { found = true; break; }
            if (v < rowv) lo = mid + 1; else hi = mid - 1;
        }
        out[row] = found ? (float)rowv : (float)g_hub64[bi];
    }
}

static inline long isqrtl(long v) {
    long r = (long)(sqrt((double)v) + 0.5);
    while (r * r > v) r--;
    while ((r + 1) * (r + 1) <= v) r++;
    return r;
}

// ===========================================================================
extern "C" void kernel_launch(void* const* d_in, const int* in_sizes, int n_in,
                              void* d_out, int out_size)
{
    long sz[16];
    int ord[16];
    int n = n_in > 16 ? 16 : n_in;
    for (int i = 0; i < n; i++) { sz[i] = (long)(unsigned)in_sizes[i]; ord[i] = i; }
    for (int a = 0; a < n; a++)
        for (int b = a + 1; b < n; b++)
            if (sz[ord[b]] > sz[ord[a]]) { int t = ord[a]; ord[a] = ord[b]; ord[b] = t; }

    const int sX = ord[0];
    const int wA = ord[1], wB = ord[2];
    const int sH = ord[n - 1];
    const int bA = (n >= 6) ? ord[3] : ord[1];
    const int bB = (n >= 6) ? ord[4] : ord[2];

    long E = 0, N = 0;
    int  c32 = 0, c64 = 0, verdict_n = 0;
    {
        long Ee = isqrtl(sz[wA]);
        bool okE = (Ee > 0) && (Ee * Ee == sz[wA]) && (sz[wA] == sz[wB]) &&
                   (sz[bA] == Ee) && (sz[bB] == Ee) &&
                   (sz[sX] % Ee == 0) && (Ee % 32 == 0);
        if (okE) {
            E = Ee; N = sz[sX] / Ee;
            c32 = (int)sz[sH]; c64 = (int)sz[sH];
            verdict_n = (int)(sz[sH] / 2);
        } else {
            long Eb = isqrtl(sz[wA] / 4);
            bool okB = (Eb > 0) && (Eb * Eb * 4 == sz[wA]) && (sz[wA] == sz[wB]) &&
                       (sz[bA] == Eb * 4) && (sz[bB] == Eb * 4) &&
                       (sz[sX] % (Eb * 4) == 0) && (Eb % 32 == 0);
            if (okB) {
                E = Eb; N = sz[sX] / 4 / Eb;
                c32 = (int)(sz[sH] / 4); c64 = (int)(sz[sH] / 8);
                verdict_n = c64;
            } else {
                E = 4096; N = 16384;
                c32 = 256; c64 = 256; verdict_n = 128;
            }
        }
    }
    if (E > MAXE) E = MAXE;
    if (N > MAXN) N = MAXN;
    if (N > (long)out_size) N = (long)out_size;
    int H_max = c32 > c64 ? c32 : c64;
    if (H_max > MAXH) H_max = MAXH;
    if (c32 > MAXH) c32 = MAXH;
    if (c64 > MAXH) c64 = MAXH;

    const int wlo = wA < wB ? wA : wB, whi = wA < wB ? wB : wA;
    const int blo = bA < bB ? bA : bB, bhi = bA < bB ? bB : bA;
    const bool x_first = (sX < wlo);
    const float* X   = (const float*)d_in[sX];
    const void*  hub = d_in[sH];
    const float* Wq  = (const float*)d_in[x_first ? wlo : whi];
    const float* Wk  = (const float*)d_in[x_first ? whi : wlo];
    const float* bq  = (const float*)d_in[x_first ? blo : bhi];
    const float* bk  = (const float*)d_in[x_first ? bhi : blo];

    float *pK, *pM, *pc, *pS;
    cudaGetSymbolAddress((void**)&pK, g_K);
    cudaGetSymbolAddress((void**)&pM, g_M);
    cudaGetSymbolAddress((void**)&pc, g_c);
    cudaGetSymbolAddress((void**)&pS, g_scores);

    const int iE = (int)E, iN = (int)N;
    auto cdiv = [](int a, int b) { return (a + b - 1) / b; };

    // 0) probe + normalize
    probe_normalize_kernel<<<1, 256>>>(hub, c32, c64, verdict_n, N);

    // 1) K = X[hub] @ Wk^T + bk   [H,E]
    sgemm_db<64, 64, 32, 4, 4, true, true, true>
        <<<dim3(cdiv(iE, 64), cdiv(H_max, 64)), 256>>>(X, Wk, bk, pK, iE, -1, iE, iE);

    // 2) c[h] = bq . K[h]
    bias_c_kernel<<<H_max, 256>>>(bq, iE);

    // 3) M = K @ Wq               [H,E]
    sgemm_db<64, 64, 32, 4, 4, false, false, false>
        <<<dim3(cdiv(iE, 64), cdiv(H_max, 64)), 256>>>(pK, Wq, nullptr, pM, iE, -1, iE, iE);

    // 4+5) scores + argmax
    const bool fast_ok = (c32 == c64) && (H_max % 64 == 0) && (H_max >= 64) &&
                         (iE % 32 == 0) && (iN % 128 == 0);
    if (fast_ok) {
        mh_convert_kernel<<<2048, 256>>>(H_max, iE);
        score_mma<<<dim3(H_max / 64, iN / 128), 256>>>(X, iE, H_max);
        argmax_rescore<<<cdiv(iN * 32, 256), 256>>>(X, pM, (float*)d_out, iE, iN);
    } else {
        sgemm_db<128, 128, 16, 8, 8, true, false, true>
            <<<dim3(cdiv(H_max, 128), cdiv(iN, 128)), 256>>>(X, pM, pc, pS, iE, iN, -1, -1);
        argmax_kernel<<<cdiv(iN * 32, 256), 256>>>((float*)d_out, iN);
    }
}